// round 14
// baseline (speedup 1.0000x reference)
#include <cuda_runtime.h>
#include <math.h>

#define NNODE 4096
#define LL 500
#define LP 512
#define FEAT 800

typedef unsigned long long ull;

// ---------------- scratch (device globals; no allocation) ----------------
__device__ float g_P1[NNODE * 3840];
__device__ float g_F[NNODE * FEAT];
__device__ float g_H[NNODE * LP];
__device__ float g_sq[NNODE];
__device__ unsigned char g_bin[(size_t)NNODE * NNODE];
__device__ unsigned int g_hist[64];
__device__ int   g_kthr;
__device__ int   g_adj[(size_t)NNODE * NNODE];
__device__ int   g_deg[NNODE];
__device__ float g_invS[NNODE];
__device__ float g_invC[NNODE];
__device__ float g_AH[NNODE * LP];
__device__ float g_AHn[NNODE * LP];
__device__ float g_W[512 * 1024];
__device__ float g_part0[(size_t)NNODE * LP];
__device__ float g_part1[(size_t)NNODE * LP];
__device__ float g_Zp[NNODE * LP];
__device__ float g_S[NNODE * 8];
__device__ float g_T[NNODE * 8];
__device__ float g_cpart[8][5 * 512];
__device__ float g_coar[5 * LP];
__device__ float g_Ac[25];
__device__ float g_bnp[64 * 512];
__device__ float g_bnp2[64 * 512];
__device__ float g_bnm[512];
__device__ float g_bni[512];

__global__ void k_zero() { if (threadIdx.x < 64) g_hist[threadIdx.x] = 0u; }

// ---------------- packed fp32x2 helpers ----------------
__device__ __forceinline__ void fma2(ull &d, ull a, ull b) {
    asm("fma.rn.f32x2 %0, %1, %2, %0;" : "+l"(d) : "l"(a), "l"(b));
}
__device__ __forceinline__ ull pk2(float a, float b) {
    ull r; asm("mov.b64 %0, {%1, %2};" : "=l"(r) : "f"(a), "f"(b)); return r;
}
__device__ __forceinline__ ull dup2(float a) { return pk2(a, a); }
__device__ __forceinline__ float2 up2(ull v) {
    float2 r; r.x = __uint_as_float((unsigned)v); r.y = __uint_as_float((unsigned)(v >> 32)); return r;
}

// compute core: 128x128 tile, BK=16, plain A (packed after load), acc 8 rows x 4 col-pairs
__device__ __forceinline__ void gemm_core_p(const float (*As)[128], const float (*Bs)[128],
                                            int tx, int ty, ull acc[8][4]) {
#pragma unroll
    for (int kk = 0; kk < 16; kk++) {
        float4 a0 = *(const float4*)&As[kk][4 * ty];
        float4 a1 = *(const float4*)&As[kk][4 * ty + 64];
        ulonglong2 B01 = *(const ulonglong2*)&Bs[kk][4 * tx];
        ulonglong2 B23 = *(const ulonglong2*)&Bs[kk][4 * tx + 64];
        ull av[8] = {dup2(a0.x), dup2(a0.y), dup2(a0.z), dup2(a0.w),
                     dup2(a1.x), dup2(a1.y), dup2(a1.z), dup2(a1.w)};
        ull bv[4] = {B01.x, B01.y, B23.x, B23.y};
#pragma unroll
        for (int i = 0; i < 8; i++)
#pragma unroll
            for (int j = 0; j < 4; j++) fma2(acc[i][j], av[i], bv[j]);
    }
}
// store a register tile into smem buffer
__device__ __forceinline__ void sts_tile(float (*As)[128], float (*Bs)[128], int lrow, int lk,
                                         const float4& ra0, const float4& ra1,
                                         const float4& rb0, const float4& rb1) {
    const float* pa0 = (const float*)&ra0;
    const float* pa1 = (const float*)&ra1;
    const float* pb0 = (const float*)&rb0;
    const float* pb1 = (const float*)&rb1;
#pragma unroll
    for (int j = 0; j < 4; j++) {
        As[lk + j][lrow] = pa0[j];
        As[lk + 4 + j][lrow] = pa1[j];
        Bs[lk + j][lrow] = pb0[j];
        Bs[lk + 4 + j][lrow] = pb1[j];
    }
}

// ---------------- conv1 (1->20,5x5)+relu+pool, channel-paired f32x2 ----------------
__global__ void __launch_bounds__(384) k_conv1(const float* __restrict__ x,
                                               const float* __restrict__ w,
                                               const float* __restrict__ b) {
    int n = blockIdx.x;
    __shared__ __align__(16) float simg[784];
    __shared__ float sw[500];
    const float* xi = x + (size_t)n * 784;
    for (int i = threadIdx.x; i < 784; i += 384) simg[i] = xi[i];
    for (int i = threadIdx.x; i < 500; i += 384) sw[i] = w[i];
    __syncthreads();
    int t = threadIdx.x;
    if (t >= 360) return;
    int p = t / 36, reg = t % 36, c0 = p * 2;
    int ry = (reg / 6) * 2, rx = (reg % 6) * 2;
    ull wp[25];
#pragma unroll
    for (int u = 0; u < 25; u++) wp[u] = pk2(sw[c0 * 25 + u], sw[c0 * 25 + 25 + u]);
    ull a2[4][4];
#pragma unroll
    for (int i = 0; i < 4; i++)
#pragma unroll
        for (int j = 0; j < 4; j++) a2[i][j] = 0ULL;
#pragma unroll
    for (int rr = 0; rr < 8; rr++) {
        const float* sp = simg + (2 * ry + rr) * 28 + 2 * rx;
        float4 q0 = *(const float4*)sp;
        float4 q1 = *(const float4*)(sp + 4);
        ull rd[8] = {dup2(q0.x), dup2(q0.y), dup2(q0.z), dup2(q0.w),
                     dup2(q1.x), dup2(q1.y), dup2(q1.z), dup2(q1.w)};
        int iy0 = rr - 4 > 0 ? rr - 4 : 0, iy1 = rr < 3 ? rr : 3;
#pragma unroll 4
        for (int iy = iy0; iy <= iy1; iy++) {
            int ky = rr - iy;
#pragma unroll
            for (int ix = 0; ix < 4; ix++)
#pragma unroll
                for (int kx = 0; kx < 5; kx++) fma2(a2[iy][ix], rd[ix + kx], wp[ky * 5 + kx]);
        }
    }
    float b0 = b[c0], b1 = b[c0 + 1];
#pragma unroll
    for (int py = 0; py < 2; py++)
#pragma unroll
        for (int px = 0; px < 2; px++) {
            float2 v00 = up2(a2[2 * py][2 * px]), v01 = up2(a2[2 * py][2 * px + 1]);
            float2 v10 = up2(a2[2 * py + 1][2 * px]), v11 = up2(a2[2 * py + 1][2 * px + 1]);
            float m0 = fmaxf(fmaxf(v00.x, v01.x), fmaxf(v10.x, v11.x));
            float m1 = fmaxf(fmaxf(v00.y, v01.y), fmaxf(v10.y, v11.y));
            int yy = ry + py, xx = rx + px;
            g_P1[(size_t)n * 3840 + c0 * 192 + yy * 16 + xx] = fmaxf(m0 + b0, 0.f);
            g_P1[(size_t)n * 3840 + (c0 + 1) * 192 + yy * 16 + xx] = fmaxf(m1 + b1, 0.f);
        }
}

// ---------------- conv2: 5 images/block, channel-paired f32x2 ----------------
#define C2_IMGS 5
__global__ void __launch_bounds__(512, 1) k_conv2(const float* __restrict__ w,
                                                  const float* __restrict__ b) {
    extern __shared__ __align__(16) float sp5[];
    int n0 = blockIdx.x * C2_IMGS;
    for (int v = threadIdx.x; v < 960 * C2_IMGS; v += 512) {
        int img = v / 960, idx = v % 960;
        if (n0 + img < NNODE)
            ((float4*)(sp5 + img * 3840))[idx] = ((const float4*)(g_P1 + (size_t)(n0 + img) * 3840))[idx];
    }
    __syncthreads();
    int t = threadIdx.x;
    if (t >= 100 * C2_IMGS) return;
    int img = t / 100, t2 = t % 100, n = n0 + img;
    if (n >= NNODE) return;
    int cp = t2 >> 2, q = t2 & 3, c0 = cp * 2;
    int ry = (q >> 1) * 2, rx = (q & 1) * 2;
    ull a2[4][4];
#pragma unroll
    for (int i = 0; i < 4; i++)
#pragma unroll
        for (int j = 0; j < 4; j++) a2[i][j] = 0ULL;
    const float* sp = sp5 + img * 3840;
    for (int ic = 0; ic < 20; ic++) {
        ull wp[25];
        const float* w0 = w + c0 * 500 + ic * 25;
#pragma unroll
        for (int u = 0; u < 25; u++) wp[u] = pk2(__ldg(w0 + u), __ldg(w0 + 500 + u));
#pragma unroll
        for (int rr = 0; rr < 8; rr++) {
            const float* rp = sp + ic * 192 + (2 * ry + rr) * 16 + 2 * rx;
            float4 q0 = *(const float4*)rp;
            float4 q1 = *(const float4*)(rp + 4);
            ull rd[8] = {dup2(q0.x), dup2(q0.y), dup2(q0.z), dup2(q0.w),
                         dup2(q1.x), dup2(q1.y), dup2(q1.z), dup2(q1.w)};
            int iy0 = rr - 4 > 0 ? rr - 4 : 0, iy1 = rr < 3 ? rr : 3;
#pragma unroll 4
            for (int iy = iy0; iy <= iy1; iy++) {
                int ky = rr - iy;
#pragma unroll
                for (int ix = 0; ix < 4; ix++)
#pragma unroll
                    for (int kx = 0; kx < 5; kx++) fma2(a2[iy][ix], rd[ix + kx], wp[ky * 5 + kx]);
            }
        }
    }
    float b0 = b[c0], b1 = b[c0 + 1];
#pragma unroll
    for (int py = 0; py < 2; py++)
#pragma unroll
        for (int px = 0; px < 2; px++) {
            float2 v00 = up2(a2[2 * py][2 * px]), v01 = up2(a2[2 * py][2 * px + 1]);
            float2 v10 = up2(a2[2 * py + 1][2 * px]), v11 = up2(a2[2 * py + 1][2 * px + 1]);
            float m0 = fmaxf(fmaxf(v00.x, v01.x), fmaxf(v10.x, v11.x));
            float m1 = fmaxf(fmaxf(v00.y, v01.y), fmaxf(v10.y, v11.y));
            g_F[(size_t)n * 800 + c0 * 16 + (ry + py) * 4 + rx + px] = fmaxf(m0 + b0, 0.f);
            g_F[(size_t)n * 800 + (c0 + 1) * 16 + (ry + py) * 4 + rx + px] = fmaxf(m1 + b1, 0.f);
        }
}

// ---------------- split NT GEMM, double-buffered: z slot picks (A,B) pair ----------------
__global__ void __launch_bounds__(256, 2) k_gemm_sk(
    const float* __restrict__ A0, const float* __restrict__ A1, int lda,
    const float* __restrict__ B0, const float* __restrict__ B1, int ldb,
    int K, int Nc) {
    __shared__ float As[2][16][128];
    __shared__ float Bs[2][16][128];
    int tid = threadIdx.x, tx = tid & 15, ty = tid >> 4;
    int zz = blockIdx.z;
    const float* A = zz ? A1 : A0;
    const float* B = zz ? B1 : B0;
    float* Cp = zz ? g_part1 : g_part0;
    int brow = blockIdx.y * 128, bcol = blockIdx.x * 128;
    int lrow = tid >> 1, lk = (tid & 1) * 8;
    int gr = brow + lrow, gc = bcol + lrow;
    int bok = (gc < Nc);
    ull acc[8][4];
#pragma unroll
    for (int i = 0; i < 8; i++)
#pragma unroll
        for (int j = 0; j < 4; j++) acc[i][j] = 0ULL;
    const float4 z4 = make_float4(0.f, 0.f, 0.f, 0.f);
    float4 ra0, ra1, rb0, rb1;
    ra0 = *(const float4*)(A + (size_t)gr * lda + lk);
    ra1 = *(const float4*)(A + (size_t)gr * lda + lk + 4);
    rb0 = bok ? *(const float4*)(B + (size_t)gc * ldb + lk) : z4;
    rb1 = bok ? *(const float4*)(B + (size_t)gc * ldb + lk + 4) : z4;
    sts_tile(As[0], Bs[0], lrow, lk, ra0, ra1, rb0, rb1);
    int ktiles = K >> 4;
    for (int tt = 0; tt < ktiles; tt++) {
        __syncthreads();
        int cur = tt & 1;
        if (tt + 1 < ktiles) {
            int kb = (tt + 1) * 16 + lk;
            ra0 = *(const float4*)(A + (size_t)gr * lda + kb);
            ra1 = *(const float4*)(A + (size_t)gr * lda + kb + 4);
            rb0 = bok ? *(const float4*)(B + (size_t)gc * ldb + kb) : z4;
            rb1 = bok ? *(const float4*)(B + (size_t)gc * ldb + kb + 4) : z4;
        }
        gemm_core_p(As[cur], Bs[cur], tx, ty, acc);
        if (tt + 1 < ktiles)
            sts_tile(As[cur ^ 1], Bs[cur ^ 1], lrow, lk, ra0, ra1, rb0, rb1);
    }
#pragma unroll
    for (int i = 0; i < 8; i++) {
        int r = brow + ty * 4 + (i & 3) + ((i >> 2) << 6);
#pragma unroll
        for (int j = 0; j < 4; j++) {
            int c = bcol + tx * 4 + ((j & 1) << 1) + ((j >> 1) << 6);
            float2 v = up2(acc[i][j]);
            Cp[(size_t)r * LP + c] = v.x;
            Cp[(size_t)r * LP + c + 1] = v.y;
        }
    }
}

// ---------------- combine split parts + bias + act (+ optional row norm) ----------------
__global__ void k_comb(const float* __restrict__ bias, float* __restrict__ dst,
                       int act, int rn) {
    int i = blockIdx.x;
    int tid = threadIdx.x;
    int c = tid * 4;
    float4 o = make_float4(0.f, 0.f, 0.f, 0.f);
    if (c < LL) {
        float4 v0 = *(const float4*)&g_part0[(size_t)i * LP + c];
        float4 v1 = *(const float4*)&g_part1[(size_t)i * LP + c];
        o.x = v0.x + v1.x + bias[c];
        o.y = v0.y + v1.y + bias[c + 1];
        o.z = v0.z + v1.z + bias[c + 2];
        o.w = v0.w + v1.w + bias[c + 3];
        if (act == 1) {
            o.x = fmaxf(o.x, 0.f); o.y = fmaxf(o.y, 0.f);
            o.z = fmaxf(o.z, 0.f); o.w = fmaxf(o.w, 0.f);
        } else {
            o.x = o.x >= 0.f ? o.x : 0.01f * o.x;
            o.y = o.y >= 0.f ? o.y : 0.01f * o.y;
            o.z = o.z >= 0.f ? o.z : 0.01f * o.z;
            o.w = o.w >= 0.f ? o.w : 0.01f * o.w;
        }
    }
    *(float4*)&dst[(size_t)i * LP + c] = o;
    if (rn) {
        float s = o.x * o.x + o.y * o.y + o.z * o.z + o.w * o.w;
        int lane = tid & 31, warp = tid >> 5;
#pragma unroll
        for (int off = 16; off > 0; off >>= 1) s += __shfl_down_sync(0xffffffffu, s, off);
        __shared__ float red[4];
        if (lane == 0) red[warp] = s;
        __syncthreads();
        if (tid == 0) g_sq[i] = red[0] + red[1] + red[2] + red[3];
    }
}

// ---------------- pack [wl | wr] into g_W [512][1024] ----------------
__global__ void k_packw(const float* __restrict__ wl, const float* __restrict__ wr) {
    int n = blockIdx.x;
    for (int k = threadIdx.x; k < 1024; k += 256) {
        float v = 0.f;
        if (n < LL) {
            if (k < LL) v = wl[n * LL + k];
            else if (k >= 512 && k < 512 + LL) v = wr[n * LL + (k - 512)];
        }
        g_W[n * 1024 + k] = v;
    }
}

// ---------------- triangular Gram, double-buffered -> bins + histogram ----------------
__global__ void __launch_bounds__(256, 2) k_gram() {
    extern __shared__ __align__(16) float dsm[];
    float (*As)[16][128] = (float (*)[16][128])dsm;          // As[2]
    float (*Bs)[16][128] = (float (*)[16][128])(dsm + 4096); // Bs[2]
    __shared__ unsigned int shist[64];
    __shared__ unsigned char sbin[128][129];
    int tid = threadIdx.x, tx = tid & 15, ty = tid >> 4;
    if (tid < 64) shist[tid] = 0u;
    int bid = blockIdx.x, by = 0, rem = bid;
    while (rem >= 32 - by) { rem -= 32 - by; by++; }
    int bx = by + rem;
    int brow = by * 128, bcol = bx * 128;
    int lrow = tid >> 1, lk = (tid & 1) * 8;
    int gr = brow + lrow, gc = bcol + lrow;
    ull acc[8][4];
#pragma unroll
    for (int i = 0; i < 8; i++)
#pragma unroll
        for (int j = 0; j < 4; j++) acc[i][j] = 0ULL;
    float4 ra0, ra1, rb0, rb1;
    ra0 = *(const float4*)(g_H + (size_t)gr * LP + lk);
    ra1 = *(const float4*)(g_H + (size_t)gr * LP + lk + 4);
    rb0 = *(const float4*)(g_H + (size_t)gc * LP + lk);
    rb1 = *(const float4*)(g_H + (size_t)gc * LP + lk + 4);
    sts_tile(As[0], Bs[0], lrow, lk, ra0, ra1, rb0, rb1);
    for (int tt = 0; tt < 32; tt++) {
        __syncthreads();
        int cur = tt & 1;
        if (tt + 1 < 32) {
            int kb = (tt + 1) * 16 + lk;
            ra0 = *(const float4*)(g_H + (size_t)gr * LP + kb);
            ra1 = *(const float4*)(g_H + (size_t)gr * LP + kb + 4);
            rb0 = *(const float4*)(g_H + (size_t)gc * LP + kb);
            rb1 = *(const float4*)(g_H + (size_t)gc * LP + kb + 4);
        }
        gemm_core_p(As[cur], Bs[cur], tx, ty, acc);
        if (tt + 1 < 32)
            sts_tile(As[cur ^ 1], Bs[cur ^ 1], lrow, lk, ra0, ra1, rb0, rb1);
    }
    float sqr_[8], sqc_[8];
#pragma unroll
    for (int i = 0; i < 8; i++) sqr_[i] = g_sq[brow + ty * 4 + (i & 3) + ((i >> 2) << 6)];
#pragma unroll
    for (int j = 0; j < 8; j++) sqc_[j] = g_sq[bcol + tx * 4 + (j & 3) + ((j >> 2) << 6)];
    unsigned wgt = (bx == by) ? 1u : 2u;
#pragma unroll
    for (int i = 0; i < 8; i++) {
        int lr = ty * 4 + (i & 3) + ((i >> 2) << 6);
        int r = brow + lr;
#pragma unroll
        for (int j = 0; j < 4; j++) {
            int lcb = tx * 4 + ((j & 1) << 1) + ((j >> 1) << 6);
            float2 v = up2(acc[i][j]);
#pragma unroll
            for (int e = 0; e < 2; e++) {
                int lc = lcb + e;
                int c = bcol + lc;
                int ce = ((j >> 1) << 2) + ((j & 1) << 1) + e;
                float dot = e ? v.y : v.x;
                float d2 = fmaxf(sqr_[i] - 2.f * dot + sqc_[ce], 0.f);
                int bin;
                if (r == c) bin = 255;
                else if (d2 < 6.25f) bin = 0;
                else {
                    float d = sqrtf(d2);
                    bin = 1 + (int)((d - 2.5f) * 2.0f);
                    if (bin > 63) bin = 63;
                    float t = 2.5f + 0.5f * (float)bin;
                    if (!(d2 < t * t)) { bin++; if (bin > 63) bin = 63; }
                    else if (bin > 1) { float tm = t - 0.5f; if (d2 < tm * tm) bin--; }
                }
                sbin[lr][lc] = (unsigned char)bin;
                unsigned msk = __match_any_sync(0xffffffffu, bin);
                int leader = __ffs(msk) - 1;
                if ((int)(tid & 31) == leader && bin < 64)
                    atomicAdd(&shist[bin], (unsigned)__popc(msk) * wgt);
            }
        }
    }
    __syncthreads();
    if (tid < 64 && shist[tid]) atomicAdd(&g_hist[tid], shist[tid]);
    for (int idx = tid; idx < 1024; idx += 256) {
        int row = idx >> 3, cq = (idx & 7) * 16;
        union { unsigned char b[16]; uint4 v; } u;
#pragma unroll
        for (int k = 0; k < 16; k++) u.b[k] = sbin[row][cq + k];
        *(uint4*)&g_bin[(size_t)(brow + row) * NNODE + bcol + cq] = u.v;
    }
    if (bx != by) {
        for (int idx = tid; idx < 1024; idx += 256) {
            int row = idx >> 3, cq = (idx & 7) * 16;
            union { unsigned char b[16]; uint4 v; } u;
#pragma unroll
            for (int k = 0; k < 16; k++) u.b[k] = sbin[cq + k][row];
            *(uint4*)&g_bin[(size_t)(bcol + row) * NNODE + brow + cq] = u.v;
        }
    }
}

// ---------------- pick threshold bin ----------------
__global__ void k_thr() {
    unsigned cum = 0; int k = 0;
    for (k = 0; k < 64; k++) { cum += g_hist[k]; if ((float)cum >= 409.6f) break; }
    if (k > 63) k = 63;
    g_kthr = k;
}

// ---------------- adjacency build ----------------
__global__ void __launch_bounds__(256) k_adj() {
    int i = blockIdx.x;
    int tid = threadIdx.x, lane = tid & 31, warp = tid >> 5;
    int kthr = g_kthr;
    uint4 v = ((const uint4*)(g_bin + (size_t)i * NNODE))[tid];
    unsigned words[4] = {v.x, v.y, v.z, v.w};
    int cnt = 0; unsigned hm = 0;
#pragma unroll
    for (int wq = 0; wq < 4; wq++)
#pragma unroll
        for (int bq = 0; bq < 4; bq++) {
            int bv = (int)((words[wq] >> (bq * 8)) & 0xffu);
            bool h = (bv <= kthr);
            cnt += h ? 1 : 0;
            hm |= (h ? 1u : 0u) << (wq * 4 + bq);
        }
    int sc = cnt;
#pragma unroll
    for (int o = 1; o < 32; o <<= 1) {
        int t2 = __shfl_up_sync(0xffffffffu, sc, o);
        if (lane >= o) sc += t2;
    }
    __shared__ int wtot[8], wbase[8];
    if (lane == 31) wtot[warp] = sc;
    int excl = sc - cnt;
    __syncthreads();
    if (tid == 0) {
        int bse = 0;
        for (int w = 0; w < 8; w++) { wbase[w] = bse; bse += wtot[w]; }
        g_deg[i] = bse;
        g_invS[i] = 1.f / fmaxf((float)bse, 1.f);
        g_invC[i] = 1.f / ((float)bse + 1.f);
    }
    __syncthreads();
    int pos = wbase[warp] + excl;
    int* out = g_adj + (size_t)i * NNODE;
    int j0 = tid * 16;
#pragma unroll
    for (int u = 0; u < 16; u++)
        if ((hm >> u) & 1u) out[pos++] = j0 + u;
}

// ---------------- sparse AH gather ----------------
__global__ void __launch_bounds__(128) k_gather() {
    int i = blockIdx.x;
    int deg = g_deg[i], f = threadIdx.x * 4;
    const int* adj = g_adj + (size_t)i * NNODE;
    float4 acc = make_float4(0.f, 0.f, 0.f, 0.f);
    for (int e = 0; e < deg; e++) {
        float4 h = *(const float4*)&g_H[(size_t)adj[e] * LP + f];
        acc.x += h.x; acc.y += h.y; acc.z += h.z; acc.w += h.w;
    }
    *(float4*)&g_AH[(size_t)i * LP + f] = acc;
    float s = g_invS[i];
    *(float4*)&g_AHn[(size_t)i * LP + f] = make_float4(acc.x * s, acc.y * s, acc.z * s, acc.w * s);
}

// ---------------- BatchNorm stats (apply is fused into k_coar) ----------------
__global__ void k_bnsum() {
    int f = threadIdx.x, b = blockIdx.x;
    float s = 0.f, s2 = 0.f;
    for (int n = b; n < NNODE; n += 64) {
        float v = g_Zp[(size_t)n * LP + f];
        s += v; s2 += v * v;
    }
    g_bnp[b * 512 + f] = s; g_bnp2[b * 512 + f] = s2;
}
__global__ void k_bnfin() {
    int f = threadIdx.x;
    float s = 0.f, s2 = 0.f;
    for (int b = 0; b < 64; b++) { s += g_bnp[b * 512 + f]; s2 += g_bnp2[b * 512 + f]; }
    float m = s / (float)NNODE;
    float var = fmaxf(s2 / (float)NNODE - m * m, 0.f);
    g_bnm[f] = m; g_bni[f] = 1.f / sqrtf(var + 1e-5f);
}

// ---------------- ClusterGCN assignment (register-cached rows) ----------------
__global__ void k_cluster(const float* __restrict__ wout, const float* __restrict__ bout,
                          const float* __restrict__ wroot) {
    int warp = threadIdx.x >> 5, lane = threadIdx.x & 31;
    int i = blockIdx.x * 4 + warp;
    float invc = g_invC[i];
    float hv[16], ag[16];
#pragma unroll
    for (int u = 0; u < 16; u++) {
        int k = lane + 32 * u;
        float h = g_H[(size_t)i * LP + k];
        float a = g_AH[(size_t)i * LP + k];
        hv[u] = h; ag[u] = (a + h) * invc;
    }
    float lg[5];
#pragma unroll
    for (int c = 0; c < 5; c++) {
        float acc = 0.f;
#pragma unroll
        for (int u = 0; u < 16; u++) {
            int k = lane + 32 * u;
            if (k < LL) acc += ag[u] * __ldg(&wout[c * LL + k]) + hv[u] * __ldg(&wroot[c * LL + k]);
        }
#pragma unroll
        for (int o = 16; o > 0; o >>= 1) acc += __shfl_down_sync(0xffffffffu, acc, o);
        acc = __shfl_sync(0xffffffffu, acc, 0);
        lg[c] = acc + bout[c];
    }
    if (lane == 0) {
        float m = lg[0];
#pragma unroll
        for (int c = 1; c < 5; c++) m = fmaxf(m, lg[c]);
        float e[5], s = 0.f;
#pragma unroll
        for (int c = 0; c < 5; c++) { e[c] = expf(lg[c] - m); s += e[c]; }
#pragma unroll
        for (int c = 0; c < 5; c++) g_S[(size_t)i * 8 + c] = e[c] / s;
    }
}

// ---------------- T = A @ S via adjacency ----------------
__global__ void __launch_bounds__(256) k_ts() {
    int row = blockIdx.x * 8 + (threadIdx.x >> 5);
    int lane = threadIdx.x & 31;
    int deg = g_deg[row];
    const int* adj = g_adj + (size_t)row * NNODE;
    float a0 = 0.f, a1 = 0.f, a2 = 0.f, a3 = 0.f, a4 = 0.f;
    for (int e = lane; e < deg; e += 32) {
        const float* s = g_S + (size_t)adj[e] * 8;
        a0 += s[0]; a1 += s[1]; a2 += s[2]; a3 += s[3]; a4 += s[4];
    }
#pragma unroll
    for (int o = 16; o > 0; o >>= 1) {
        a0 += __shfl_down_sync(0xffffffffu, a0, o);
        a1 += __shfl_down_sync(0xffffffffu, a1, o);
        a2 += __shfl_down_sync(0xffffffffu, a2, o);
        a3 += __shfl_down_sync(0xffffffffu, a3, o);
        a4 += __shfl_down_sync(0xffffffffu, a4, o);
    }
    if (lane == 0) {
        float* t = g_T + (size_t)row * 8;
        t[0] = a0; t[1] = a1; t[2] = a2; t[3] = a3; t[4] = a4;
    }
}

// ---------------- coar partials = S^T @ BN(Zp) (BN applied inline, exact order) ----------------
__global__ void k_coar(const float* __restrict__ bng, const float* __restrict__ bnb) {
    int fx = threadIdx.x & 63, ny = threadIdx.x >> 6;
    int f = blockIdx.x * 64 + fx, n0 = blockIdx.y * 512;
    float m = g_bnm[f], inv = g_bni[f];
    float gf = (f < LL) ? bng[f] : 0.f;
    float bf = (f < LL) ? bnb[f] : 0.f;
    float acc[5] = {0.f, 0.f, 0.f, 0.f, 0.f};
    for (int n = n0 + ny; n < n0 + 512; n += 4) {
        float v = g_Zp[(size_t)n * LP + f];
        float z = (v - m) * inv * gf + bf;
        const float* s = g_S + (size_t)n * 8;
#pragma unroll
        for (int c = 0; c < 5; c++) acc[c] += s[c] * z;
    }
    __shared__ float red[4][64][5];
#pragma unroll
    for (int c = 0; c < 5; c++) red[ny][fx][c] = acc[c];
    __syncthreads();
    if (ny == 0)
#pragma unroll
        for (int c = 0; c < 5; c++)
            g_cpart[blockIdx.y][c * 512 + f] = red[0][fx][c] + red[1][fx][c] + red[2][fx][c] + red[3][fx][c];
}
__global__ void k_coarfin() {
    int c = blockIdx.x, f = threadIdx.x;
    float s = 0.f;
    for (int b = 0; b < 8; b++) s += g_cpart[b][c * 512 + f];
    g_coar[c * LP + f] = s;
}

// ---------------- Ac = S^T @ T ----------------
__global__ void k_ac() {
    int tid = threadIdx.x, lane = tid & 31, warp = tid >> 5;
    float acc[25];
#pragma unroll
    for (int q = 0; q < 25; q++) acc[q] = 0.f;
    for (int n = tid; n < NNODE; n += 256) {
        float sv[5], tv[5];
#pragma unroll
        for (int c = 0; c < 5; c++) { sv[c] = g_S[(size_t)n * 8 + c]; tv[c] = g_T[(size_t)n * 8 + c]; }
#pragma unroll
        for (int a = 0; a < 5; a++)
#pragma unroll
            for (int b = 0; b < 5; b++) acc[a * 5 + b] += sv[a] * tv[b];
    }
#pragma unroll
    for (int q = 0; q < 25; q++)
#pragma unroll
        for (int o = 16; o > 0; o >>= 1) acc[q] += __shfl_down_sync(0xffffffffu, acc[q], o);
    __shared__ float red[8][25];
    if (lane == 0)
#pragma unroll
        for (int q = 0; q < 25; q++) red[warp][q] = acc[q];
    __syncthreads();
    if (tid < 25) {
        float s = 0.f;
#pragma unroll
        for (int w = 0; w < 8; w++) s += red[w][tid];
        g_Ac[tid] = s;
    }
}

// ---------------- final: coarse SAGE + BN + pool + MLP + softmax ----------------
__global__ void __launch_bounds__(512) k_final(
    const float* __restrict__ wl, const float* __restrict__ bl, const float* __restrict__ wr,
    const float* __restrict__ bng, const float* __restrict__ bnb,
    const float* __restrict__ l1w, const float* __restrict__ l1b,
    const float* __restrict__ l2w, const float* __restrict__ l2b,
    float* __restrict__ out, int out_size) {
    __shared__ float Mc[25], invdc[5], neigh[2500], pre[2500], h1[1250], lg[5];
    int tid = threadIdx.x;
    if (tid == 0) {
        float mean = 0.f;
        for (int q = 0; q < 25; q++) mean += g_Ac[q];
        mean *= (1.f / 25.f);
        for (int q = 0; q < 25; q++) Mc[q] = (g_Ac[q] >= mean && g_Ac[q] > 0.f) ? 1.f : 0.f;
        for (int i = 0; i < 5; i++) {
            float d = 0.f;
            for (int j = 0; j < 5; j++) d += Mc[i * 5 + j];
            invdc[i] = 1.f / fmaxf(d, 1.f);
        }
    }
    __syncthreads();
    for (int idx = tid; idx < 2500; idx += 512) {
        int i = idx / 500, f = idx % 500;
        float a = 0.f;
#pragma unroll
        for (int j = 0; j < 5; j++) a += Mc[i * 5 + j] * g_coar[j * LP + f];
        neigh[idx] = a * invdc[i];
    }
    __syncthreads();
    for (int idx = tid; idx < 2500; idx += 512) {
        int i = idx / 500, f = idx % 500;
        const float* wlr = wl + f * 500;
        const float* wrr = wr + f * 500;
        float a0 = 0.f, a1 = 0.f, a2 = 0.f, a3 = 0.f;
        for (int k = 0; k < 500; k += 4) {
            a0 += neigh[i * 500 + k] * wlr[k] + g_coar[i * LP + k] * wrr[k];
            a1 += neigh[i * 500 + k + 1] * wlr[k + 1] + g_coar[i * LP + k + 1] * wrr[k + 1];
            a2 += neigh[i * 500 + k + 2] * wlr[k + 2] + g_coar[i * LP + k + 2] * wrr[k + 2];
            a3 += neigh[i * 500 + k + 3] * wlr[k + 3] + g_coar[i * LP + k + 3] * wrr[k + 3];
        }
        float acc = bl[f] + ((a0 + a1) + (a2 + a3));
        pre[idx] = (acc >= 0.f) ? acc : 0.01f * acc;
    }
    __syncthreads();
    for (int f = tid; f < 500; f += 512) {
        float m = 0.f;
#pragma unroll
        for (int i = 0; i < 5; i++) m += pre[i * 500 + f];
        m *= 0.2f;
        float v = 0.f;
#pragma unroll
        for (int i = 0; i < 5; i++) { float d = pre[i * 500 + f] - m; v += d * d; }
        v *= 0.2f;
        float sd = sqrtf(v + 1e-5f);
        float gf = bng[f], bf = bnb[f];
#pragma unroll
        for (int i = 0; i < 5; i++) pre[i * 500 + f] = (pre[i * 500 + f] - m) / sd * gf + bf;
    }
    __syncthreads();
    for (int idx = tid; idx < 2500; idx += 512) {
        int i = idx / 500, f = idx % 500;
        float mx = -1e30f;
#pragma unroll
        for (int j = 0; j < 5; j++)
            if (Mc[i * 5 + j] > 0.f || j == i) mx = fmaxf(mx, pre[j * 500 + f]);
        neigh[idx] = mx;
    }
    __syncthreads();
    for (int idx = tid; idx < 1250; idx += 512) {
        int i = idx / 250, o = idx % 250;
        const float* w = l1w + o * 500;
        float a0 = 0.f, a1 = 0.f, a2 = 0.f, a3 = 0.f;
        for (int k = 0; k < 500; k += 4) {
            a0 += neigh[i * 500 + k] * w[k];
            a1 += neigh[i * 500 + k + 1] * w[k + 1];
            a2 += neigh[i * 500 + k + 2] * w[k + 2];
            a3 += neigh[i * 500 + k + 3] * w[k + 3];
        }
        float acc = l1b[o] + ((a0 + a1) + (a2 + a3));
        h1[idx] = (acc >= 0.f) ? acc : 0.01f * acc;
    }
    __syncthreads();
    if (tid < 5) {
        float acc = l2b[0];
        for (int k = 0; k < 250; k++) acc += h1[tid * 250 + k] * l2w[k];
        lg[tid] = (acc >= 0.f) ? acc : 0.01f * acc;
    }
    __syncthreads();
    if (tid == 0) {
        float m = lg[0];
        for (int i = 1; i < 5; i++) m = fmaxf(m, lg[i]);
        float e[5], s = 0.f;
        for (int i = 0; i < 5; i++) { e[i] = expf(lg[i] - m); s += e[i]; }
        float p = 0.f;
        for (int i = 0; i < 5; i++) p = fmaxf(p, e[i] / s);
        out[0] = p;
        if (out_size > 1) out[1] = (p >= 0.5f) ? 1.f : 0.f;
    }
}

// ---------------- host launcher ----------------
static float* symaddr(const void* sym) {
    void* p = nullptr;
    cudaGetSymbolAddress(&p, sym);
    return (float*)p;
}

extern "C" void kernel_launch(void* const* d_in, const int* in_sizes, int n_in,
                              void* d_out, int out_size) {
    const float* x    = (const float*)d_in[0];
    const float* c1w  = (const float*)d_in[1];
    const float* c1b  = (const float*)d_in[2];
    const float* c2w  = (const float*)d_in[3];
    const float* c2b  = (const float*)d_in[4];
    const float* fcw  = (const float*)d_in[5];
    const float* fcb  = (const float*)d_in[6];
    const float* swl  = (const float*)d_in[7];
    const float* sbl  = (const float*)d_in[8];
    const float* swr  = (const float*)d_in[9];
    const float* bng  = (const float*)d_in[10];
    const float* bnb  = (const float*)d_in[11];
    const float* cgwo = (const float*)d_in[12];
    const float* cgbo = (const float*)d_in[13];
    const float* cgwr = (const float*)d_in[14];
    const float* l1w  = (const float*)d_in[15];
    const float* l1b  = (const float*)d_in[16];
    const float* l2w  = (const float*)d_in[17];
    const float* l2b  = (const float*)d_in[18];
    float* out = (float*)d_out;

    float* pF   = symaddr(g_F);
    float* pH   = symaddr(g_H);
    float* pAHn = symaddr(g_AHn);
    float* pZp  = symaddr(g_Zp);
    float* pW   = symaddr(g_W);

    const int c2_smem = C2_IMGS * 3840 * (int)sizeof(float);
    const int gram_smem = 2 * 2 * 16 * 128 * (int)sizeof(float);   // 32 KB
    cudaFuncSetAttribute(k_conv2, cudaFuncAttributeMaxDynamicSharedMemorySize, c2_smem);
    cudaFuncSetAttribute(k_gram, cudaFuncAttributeMaxDynamicSharedMemorySize, gram_smem);

    k_zero<<<1, 64>>>();
    k_packw<<<512, 256>>>(swl, swr);
    k_conv1<<<NNODE, 384>>>(x, c1w, c1b);
    k_conv2<<<(NNODE + C2_IMGS - 1) / C2_IMGS, 512, c2_smem>>>(c2w, c2b);
    {   // fc: H = relu(F @ fcw^T + fcb), split-K 2 (400+400); fused row norms
        dim3 g(4, 32, 2);
        k_gemm_sk<<<g, 256>>>(pF, pF + 400, FEAT, fcw, fcw + 400, FEAT, 400, LL);
        k_comb<<<NNODE, 128>>>(fcb, pH, 1, 1);
    }
    k_gram<<<528, 256, gram_smem>>>();
    k_thr<<<1, 1>>>();
    k_adj<<<NNODE, 256>>>();
    k_gather<<<NNODE, 128>>>();
    {   // SAGE: Zp = leaky(AHn@wl^T + H@wr^T + bl), two slots of packed W
        dim3 g(4, 32, 2);
        k_gemm_sk<<<g, 256>>>(pAHn, pH, LP, pW, pW + 512, 1024, 512, LP);
        k_comb<<<NNODE, 128>>>(sbl, pZp, 2, 0);
    }
    k_bnsum<<<64, 512>>>();
    k_bnfin<<<1, 512>>>();
    k_cluster<<<NNODE / 4, 128>>>(cgwo, cgbo, cgwr);
    k_ts<<<NNODE / 8, 256>>>();
    {
        dim3 g(8, 8);
        k_coar<<<g, 256>>>(bng, bnb);
        k_coarfin<<<5, 512>>>();
    }
    k_ac<<<1, 256>>>();
    k_final<<<1, 512>>>(swl, sbl, swr, bng, bnb, l1w, l1b, l2w, l2b, out, out_size);
}

// round 15
// speedup vs baseline: 1.0248x; 1.0248x over previous
#include <cuda_runtime.h>
#include <math.h>

#define NNODE 4096
#define LL 500
#define LP 512
#define FEAT 800

typedef unsigned long long ull;

// ---------------- scratch (device globals; no allocation) ----------------
__device__ float g_P1[NNODE * 3840];
__device__ float g_F[NNODE * FEAT];
__device__ float g_H[NNODE * LP];
__device__ float g_sq[NNODE];
__device__ unsigned char g_bin[(size_t)NNODE * NNODE];
__device__ unsigned int g_hist[64];
__device__ int   g_kthr;
__device__ int   g_adj[(size_t)NNODE * NNODE];
__device__ int   g_deg[NNODE];
__device__ float g_invS[NNODE];
__device__ float g_invC[NNODE];
__device__ float g_AH[NNODE * LP];
__device__ float g_AHn[NNODE * LP];
__device__ float g_W[512 * 1024];
__device__ ull   g_c2w[25 * 20 * 25];          // packed conv2 weights [cp][ic][tap]
__device__ float g_part0[(size_t)NNODE * LP];
__device__ float g_part1[(size_t)NNODE * LP];
__device__ float g_Zp[NNODE * LP];
__device__ float g_S[NNODE * 8];
__device__ float g_T[NNODE * 8];
__device__ float g_cpart[8][5 * 512];
__device__ float g_coar[5 * LP];
__device__ float g_Ac[25];
__device__ float g_bnp[64 * 512];
__device__ float g_bnp2[64 * 512];
__device__ float g_bnm[512];
__device__ float g_bni[512];

__global__ void k_zero() { if (threadIdx.x < 64) g_hist[threadIdx.x] = 0u; }

// ---------------- packed fp32x2 helpers ----------------
__device__ __forceinline__ void fma2(ull &d, ull a, ull b) {
    asm("fma.rn.f32x2 %0, %1, %2, %0;" : "+l"(d) : "l"(a), "l"(b));
}
__device__ __forceinline__ ull pk2(float a, float b) {
    ull r; asm("mov.b64 %0, {%1, %2};" : "=l"(r) : "f"(a), "f"(b)); return r;
}
__device__ __forceinline__ ull dup2(float a) { return pk2(a, a); }
__device__ __forceinline__ float2 up2(ull v) {
    float2 r; r.x = __uint_as_float((unsigned)v); r.y = __uint_as_float((unsigned)(v >> 32)); return r;
}

// compute core: 128x128 tile, BK=16, plain A (packed after load), acc 8 rows x 4 col-pairs
__device__ __forceinline__ void gemm_core_p(const float (*As)[128], const float (*Bs)[128],
                                            int tx, int ty, ull acc[8][4]) {
#pragma unroll
    for (int kk = 0; kk < 16; kk++) {
        float4 a0 = *(const float4*)&As[kk][4 * ty];
        float4 a1 = *(const float4*)&As[kk][4 * ty + 64];
        ulonglong2 B01 = *(const ulonglong2*)&Bs[kk][4 * tx];
        ulonglong2 B23 = *(const ulonglong2*)&Bs[kk][4 * tx + 64];
        ull av[8] = {dup2(a0.x), dup2(a0.y), dup2(a0.z), dup2(a0.w),
                     dup2(a1.x), dup2(a1.y), dup2(a1.z), dup2(a1.w)};
        ull bv[4] = {B01.x, B01.y, B23.x, B23.y};
#pragma unroll
        for (int i = 0; i < 8; i++)
#pragma unroll
            for (int j = 0; j < 4; j++) fma2(acc[i][j], av[i], bv[j]);
    }
}

// ---------------- pack conv2 weights into channel pairs ----------------
__global__ void k_packc2(const float* __restrict__ w) {
    int cp = blockIdx.x;                 // 0..24
    for (int i = threadIdx.x; i < 500; i += 256)   // ic*25 + tap
        g_c2w[cp * 500 + i] = pk2(w[(2 * cp) * 500 + i], w[(2 * cp + 1) * 500 + i]);
}

// ---------------- conv1 (1->20,5x5)+relu+pool, channel-paired f32x2 ----------------
__global__ void __launch_bounds__(384) k_conv1(const float* __restrict__ x,
                                               const float* __restrict__ w,
                                               const float* __restrict__ b) {
    int n = blockIdx.x;
    __shared__ __align__(16) float simg[784];
    __shared__ float sw[500];
    const float* xi = x + (size_t)n * 784;
    for (int i = threadIdx.x; i < 784; i += 384) simg[i] = xi[i];
    for (int i = threadIdx.x; i < 500; i += 384) sw[i] = w[i];
    __syncthreads();
    int t = threadIdx.x;
    if (t >= 360) return;
    int p = t / 36, reg = t % 36, c0 = p * 2;
    int ry = (reg / 6) * 2, rx = (reg % 6) * 2;
    ull wp[25];
#pragma unroll
    for (int u = 0; u < 25; u++) wp[u] = pk2(sw[c0 * 25 + u], sw[c0 * 25 + 25 + u]);
    ull a2[4][4];
#pragma unroll
    for (int i = 0; i < 4; i++)
#pragma unroll
        for (int j = 0; j < 4; j++) a2[i][j] = 0ULL;
#pragma unroll
    for (int rr = 0; rr < 8; rr++) {
        const float* sp = simg + (2 * ry + rr) * 28 + 2 * rx;
        float4 q0 = *(const float4*)sp;
        float4 q1 = *(const float4*)(sp + 4);
        ull rd[8] = {dup2(q0.x), dup2(q0.y), dup2(q0.z), dup2(q0.w),
                     dup2(q1.x), dup2(q1.y), dup2(q1.z), dup2(q1.w)};
        int iy0 = rr - 4 > 0 ? rr - 4 : 0, iy1 = rr < 3 ? rr : 3;
#pragma unroll 4
        for (int iy = iy0; iy <= iy1; iy++) {
            int ky = rr - iy;
#pragma unroll
            for (int ix = 0; ix < 4; ix++)
#pragma unroll
                for (int kx = 0; kx < 5; kx++) fma2(a2[iy][ix], rd[ix + kx], wp[ky * 5 + kx]);
        }
    }
    float b0 = b[c0], b1 = b[c0 + 1];
#pragma unroll
    for (int py = 0; py < 2; py++)
#pragma unroll
        for (int px = 0; px < 2; px++) {
            float2 v00 = up2(a2[2 * py][2 * px]), v01 = up2(a2[2 * py][2 * px + 1]);
            float2 v10 = up2(a2[2 * py + 1][2 * px]), v11 = up2(a2[2 * py + 1][2 * px + 1]);
            float m0 = fmaxf(fmaxf(v00.x, v01.x), fmaxf(v10.x, v11.x));
            float m1 = fmaxf(fmaxf(v00.y, v01.y), fmaxf(v10.y, v11.y));
            int yy = ry + py, xx = rx + px;
            g_P1[(size_t)n * 3840 + c0 * 192 + yy * 16 + xx] = fmaxf(m0 + b0, 0.f);
            g_P1[(size_t)n * 3840 + (c0 + 1) * 192 + yy * 16 + xx] = fmaxf(m1 + b1, 0.f);
        }
}

// ---------------- conv2: 5 images/block, channel-paired f32x2, packed weights ----------------
#define C2_IMGS 5
__global__ void __launch_bounds__(512, 1) k_conv2(const float* __restrict__ b) {
    extern __shared__ __align__(16) float sp5[];
    int n0 = blockIdx.x * C2_IMGS;
    for (int v = threadIdx.x; v < 960 * C2_IMGS; v += 512) {
        int img = v / 960, idx = v % 960;
        if (n0 + img < NNODE)
            ((float4*)(sp5 + img * 3840))[idx] = ((const float4*)(g_P1 + (size_t)(n0 + img) * 3840))[idx];
    }
    __syncthreads();
    int t = threadIdx.x;
    if (t >= 100 * C2_IMGS) return;
    int img = t / 100, t2 = t % 100, n = n0 + img;
    if (n >= NNODE) return;
    int cp = t2 >> 2, q = t2 & 3, c0 = cp * 2;
    int ry = (q >> 1) * 2, rx = (q & 1) * 2;
    ull a2[4][4];
#pragma unroll
    for (int i = 0; i < 4; i++)
#pragma unroll
        for (int j = 0; j < 4; j++) a2[i][j] = 0ULL;
    const float* sp = sp5 + img * 3840;
    const ull* pw = g_c2w + cp * 500;
    for (int ic = 0; ic < 20; ic++) {
        ull wp[25];
        const ull* w0 = pw + ic * 25;
#pragma unroll
        for (int u = 0; u < 25; u++) wp[u] = __ldg(w0 + u);
#pragma unroll
        for (int rr = 0; rr < 8; rr++) {
            const float* rp = sp + ic * 192 + (2 * ry + rr) * 16 + 2 * rx;
            float4 q0 = *(const float4*)rp;
            float4 q1 = *(const float4*)(rp + 4);
            ull rd[8] = {dup2(q0.x), dup2(q0.y), dup2(q0.z), dup2(q0.w),
                         dup2(q1.x), dup2(q1.y), dup2(q1.z), dup2(q1.w)};
            int iy0 = rr - 4 > 0 ? rr - 4 : 0, iy1 = rr < 3 ? rr : 3;
#pragma unroll 4
            for (int iy = iy0; iy <= iy1; iy++) {
                int ky = rr - iy;
#pragma unroll
                for (int ix = 0; ix < 4; ix++)
#pragma unroll
                    for (int kx = 0; kx < 5; kx++) fma2(a2[iy][ix], rd[ix + kx], wp[ky * 5 + kx]);
            }
        }
    }
    float b0 = b[c0], b1 = b[c0 + 1];
#pragma unroll
    for (int py = 0; py < 2; py++)
#pragma unroll
        for (int px = 0; px < 2; px++) {
            float2 v00 = up2(a2[2 * py][2 * px]), v01 = up2(a2[2 * py][2 * px + 1]);
            float2 v10 = up2(a2[2 * py + 1][2 * px]), v11 = up2(a2[2 * py + 1][2 * px + 1]);
            float m0 = fmaxf(fmaxf(v00.x, v01.x), fmaxf(v10.x, v11.x));
            float m1 = fmaxf(fmaxf(v00.y, v01.y), fmaxf(v10.y, v11.y));
            g_F[(size_t)n * 800 + c0 * 16 + (ry + py) * 4 + rx + px] = fmaxf(m0 + b0, 0.f);
            g_F[(size_t)n * 800 + (c0 + 1) * 16 + (ry + py) * 4 + rx + px] = fmaxf(m1 + b1, 0.f);
        }
}

// ---------------- split NT GEMM: z slot picks (A,B) pair, raw partial out ----------------
__global__ void __launch_bounds__(256, 2) k_gemm_sk(
    const float* __restrict__ A0, const float* __restrict__ A1, int lda,
    const float* __restrict__ B0, const float* __restrict__ B1, int ldb,
    int K, int Nc) {
    __shared__ float As[16][128];
    __shared__ float Bs[16][128];
    int tid = threadIdx.x, tx = tid & 15, ty = tid >> 4;
    int zz = blockIdx.z;
    const float* A = zz ? A1 : A0;
    const float* B = zz ? B1 : B0;
    float* Cp = zz ? g_part1 : g_part0;
    int brow = blockIdx.y * 128, bcol = blockIdx.x * 128;
    int lrow = tid >> 1, lk = (tid & 1) * 8;
    int gr = brow + lrow, gc = bcol + lrow;
    int bok = (gc < Nc);
    ull acc[8][4];
#pragma unroll
    for (int i = 0; i < 8; i++)
#pragma unroll
        for (int j = 0; j < 4; j++) acc[i][j] = 0ULL;
    const float4 z4 = make_float4(0.f, 0.f, 0.f, 0.f);
    float4 ra0, ra1, rb0, rb1;
    ra0 = *(const float4*)(A + (size_t)gr * lda + lk);
    ra1 = *(const float4*)(A + (size_t)gr * lda + lk + 4);
    rb0 = bok ? *(const float4*)(B + (size_t)gc * ldb + lk) : z4;
    rb1 = bok ? *(const float4*)(B + (size_t)gc * ldb + lk + 4) : z4;
    int ktiles = K >> 4;
    for (int tt = 0; tt < ktiles; tt++) {
        __syncthreads();
        const float* pa0 = (const float*)&ra0;
        const float* pa1 = (const float*)&ra1;
        const float* pb0 = (const float*)&rb0;
        const float* pb1 = (const float*)&rb1;
#pragma unroll
        for (int j = 0; j < 4; j++) {
            As[lk + j][lrow] = pa0[j];
            As[lk + 4 + j][lrow] = pa1[j];
            Bs[lk + j][lrow] = pb0[j];
            Bs[lk + 4 + j][lrow] = pb1[j];
        }
        __syncthreads();
        if (tt + 1 < ktiles) {
            int kb = (tt + 1) * 16 + lk;
            ra0 = *(const float4*)(A + (size_t)gr * lda + kb);
            ra1 = *(const float4*)(A + (size_t)gr * lda + kb + 4);
            rb0 = bok ? *(const float4*)(B + (size_t)gc * ldb + kb) : z4;
            rb1 = bok ? *(const float4*)(B + (size_t)gc * ldb + kb + 4) : z4;
        }
        gemm_core_p(As, Bs, tx, ty, acc);
    }
#pragma unroll
    for (int i = 0; i < 8; i++) {
        int r = brow + ty * 4 + (i & 3) + ((i >> 2) << 6);
#pragma unroll
        for (int j = 0; j < 4; j++) {
            int c = bcol + tx * 4 + ((j & 1) << 1) + ((j >> 1) << 6);
            float2 v = up2(acc[i][j]);
            Cp[(size_t)r * LP + c] = v.x;
            Cp[(size_t)r * LP + c + 1] = v.y;
        }
    }
}

// ---------------- combine split parts + bias + act (+ optional row norm) ----------------
__global__ void k_comb(const float* __restrict__ bias, float* __restrict__ dst,
                       int act, int rn) {
    int i = blockIdx.x;
    int tid = threadIdx.x;
    int c = tid * 4;
    float4 o = make_float4(0.f, 0.f, 0.f, 0.f);
    if (c < LL) {
        float4 v0 = *(const float4*)&g_part0[(size_t)i * LP + c];
        float4 v1 = *(const float4*)&g_part1[(size_t)i * LP + c];
        o.x = v0.x + v1.x + bias[c];
        o.y = v0.y + v1.y + bias[c + 1];
        o.z = v0.z + v1.z + bias[c + 2];
        o.w = v0.w + v1.w + bias[c + 3];
        if (act == 1) {
            o.x = fmaxf(o.x, 0.f); o.y = fmaxf(o.y, 0.f);
            o.z = fmaxf(o.z, 0.f); o.w = fmaxf(o.w, 0.f);
        } else {
            o.x = o.x >= 0.f ? o.x : 0.01f * o.x;
            o.y = o.y >= 0.f ? o.y : 0.01f * o.y;
            o.z = o.z >= 0.f ? o.z : 0.01f * o.z;
            o.w = o.w >= 0.f ? o.w : 0.01f * o.w;
        }
    }
    *(float4*)&dst[(size_t)i * LP + c] = o;
    if (rn) {
        float s = o.x * o.x + o.y * o.y + o.z * o.z + o.w * o.w;
        int lane = tid & 31, warp = tid >> 5;
#pragma unroll
        for (int off = 16; off > 0; off >>= 1) s += __shfl_down_sync(0xffffffffu, s, off);
        __shared__ float red[4];
        if (lane == 0) red[warp] = s;
        __syncthreads();
        if (tid == 0) g_sq[i] = red[0] + red[1] + red[2] + red[3];
    }
}

// ---------------- pack [wl | wr] into g_W [512][1024] ----------------
__global__ void k_packw(const float* __restrict__ wl, const float* __restrict__ wr) {
    int n = blockIdx.x;
    for (int k = threadIdx.x; k < 1024; k += 256) {
        float v = 0.f;
        if (n < LL) {
            if (k < LL) v = wl[n * LL + k];
            else if (k >= 512 && k < 512 + LL) v = wr[n * LL + (k - 512)];
        }
        g_W[n * 1024 + k] = v;
    }
}

// ---------------- triangular Gram -> bins (smem-staged coalesced) + histogram ----------------
__global__ void __launch_bounds__(256, 2) k_gram() {
    __shared__ float As[16][128];
    __shared__ float Bs[16][128];
    __shared__ unsigned int shist[64];
    __shared__ unsigned char sbin[128][132];
    int tid = threadIdx.x, tx = tid & 15, ty = tid >> 4;
    if (tid < 64) shist[tid] = 0u;
    int bid = blockIdx.x, by = 0, rem = bid;
    while (rem >= 32 - by) { rem -= 32 - by; by++; }
    int bx = by + rem;
    int brow = by * 128, bcol = bx * 128;
    int lrow = tid >> 1, lk = (tid & 1) * 8;
    int gr = brow + lrow, gc = bcol + lrow;
    ull acc[8][4];
#pragma unroll
    for (int i = 0; i < 8; i++)
#pragma unroll
        for (int j = 0; j < 4; j++) acc[i][j] = 0ULL;
    float4 ra0, ra1, rb0, rb1;
    ra0 = *(const float4*)(g_H + (size_t)gr * LP + lk);
    ra1 = *(const float4*)(g_H + (size_t)gr * LP + lk + 4);
    rb0 = *(const float4*)(g_H + (size_t)gc * LP + lk);
    rb1 = *(const float4*)(g_H + (size_t)gc * LP + lk + 4);
    for (int tt = 0; tt < 32; tt++) {
        __syncthreads();
        const float* pa0 = (const float*)&ra0;
        const float* pa1 = (const float*)&ra1;
        const float* pb0 = (const float*)&rb0;
        const float* pb1 = (const float*)&rb1;
#pragma unroll
        for (int j = 0; j < 4; j++) {
            As[lk + j][lrow] = pa0[j];
            As[lk + 4 + j][lrow] = pa1[j];
            Bs[lk + j][lrow] = pb0[j];
            Bs[lk + 4 + j][lrow] = pb1[j];
        }
        __syncthreads();
        if (tt + 1 < 32) {
            int kb = (tt + 1) * 16 + lk;
            ra0 = *(const float4*)(g_H + (size_t)gr * LP + kb);
            ra1 = *(const float4*)(g_H + (size_t)gr * LP + kb + 4);
            rb0 = *(const float4*)(g_H + (size_t)gc * LP + kb);
            rb1 = *(const float4*)(g_H + (size_t)gc * LP + kb + 4);
        }
        gemm_core_p(As, Bs, tx, ty, acc);
    }
    float sqr_[8], sqc_[8];
#pragma unroll
    for (int i = 0; i < 8; i++) sqr_[i] = g_sq[brow + ty * 4 + (i & 3) + ((i >> 2) << 6)];
#pragma unroll
    for (int j = 0; j < 8; j++) sqc_[j] = g_sq[bcol + tx * 4 + (j & 3) + ((j >> 2) << 6)];
    unsigned wgt = (bx == by) ? 1u : 2u;
#pragma unroll
    for (int i = 0; i < 8; i++) {
        int lr = ty * 4 + (i & 3) + ((i >> 2) << 6);
        int r = brow + lr;
#pragma unroll
        for (int j = 0; j < 4; j++) {
            int lcb = tx * 4 + ((j & 1) << 1) + ((j >> 1) << 6);
            float2 v = up2(acc[i][j]);
#pragma unroll
            for (int e = 0; e < 2; e++) {
                int lc = lcb + e;
                int c = bcol + lc;
                int ce = ((j >> 1) << 2) + ((j & 1) << 1) + e;
                float dot = e ? v.y : v.x;
                float d2 = fmaxf(sqr_[i] - 2.f * dot + sqc_[ce], 0.f);
                int bin;
                if (r == c) bin = 255;
                else if (d2 < 6.25f) bin = 0;
                else {
                    float d = sqrtf(d2);
                    bin = 1 + (int)((d - 2.5f) * 2.0f);
                    if (bin > 63) bin = 63;
                    float t = 2.5f + 0.5f * (float)bin;
                    if (!(d2 < t * t)) { bin++; if (bin > 63) bin = 63; }
                    else if (bin > 1) { float tm = t - 0.5f; if (d2 < tm * tm) bin--; }
                }
                sbin[lr][lc] = (unsigned char)bin;
                unsigned msk = __match_any_sync(0xffffffffu, bin);
                int leader = __ffs(msk) - 1;
                if ((int)(tid & 31) == leader && bin < 64)
                    atomicAdd(&shist[bin], (unsigned)__popc(msk) * wgt);
            }
        }
    }
    __syncthreads();
    if (tid < 64 && shist[tid]) atomicAdd(&g_hist[tid], shist[tid]);
    for (int idx = tid; idx < 1024; idx += 256) {
        int row = idx >> 3, cq = (idx & 7) * 16;
        union { unsigned char b[16]; uint4 v; } u;
#pragma unroll
        for (int k = 0; k < 16; k++) u.b[k] = sbin[row][cq + k];
        *(uint4*)&g_bin[(size_t)(brow + row) * NNODE + bcol + cq] = u.v;
    }
    if (bx != by) {
        for (int idx = tid; idx < 1024; idx += 256) {
            int row = idx >> 3, cq = (idx & 7) * 16;
            union { unsigned char b[16]; uint4 v; } u;
#pragma unroll
            for (int k = 0; k < 16; k++) u.b[k] = sbin[cq + k][row];
            *(uint4*)&g_bin[(size_t)(bcol + row) * NNODE + brow + cq] = u.v;
        }
    }
}

// ---------------- pick threshold bin ----------------
__global__ void k_thr() {
    unsigned cum = 0; int k = 0;
    for (k = 0; k < 64; k++) { cum += g_hist[k]; if ((float)cum >= 409.6f) break; }
    if (k > 63) k = 63;
    g_kthr = k;
}

// ---------------- adjacency build ----------------
__global__ void __launch_bounds__(256) k_adj() {
    int i = blockIdx.x;
    int tid = threadIdx.x, lane = tid & 31, warp = tid >> 5;
    int kthr = g_kthr;
    uint4 v = ((const uint4*)(g_bin + (size_t)i * NNODE))[tid];
    unsigned words[4] = {v.x, v.y, v.z, v.w};
    int cnt = 0; unsigned hm = 0;
#pragma unroll
    for (int wq = 0; wq < 4; wq++)
#pragma unroll
        for (int bq = 0; bq < 4; bq++) {
            int bv = (int)((words[wq] >> (bq * 8)) & 0xffu);
            bool h = (bv <= kthr);
            cnt += h ? 1 : 0;
            hm |= (h ? 1u : 0u) << (wq * 4 + bq);
        }
    int sc = cnt;
#pragma unroll
    for (int o = 1; o < 32; o <<= 1) {
        int t2 = __shfl_up_sync(0xffffffffu, sc, o);
        if (lane >= o) sc += t2;
    }
    __shared__ int wtot[8], wbase[8];
    if (lane == 31) wtot[warp] = sc;
    int excl = sc - cnt;
    __syncthreads();
    if (tid == 0) {
        int bse = 0;
        for (int w = 0; w < 8; w++) { wbase[w] = bse; bse += wtot[w]; }
        g_deg[i] = bse;
        g_invS[i] = 1.f / fmaxf((float)bse, 1.f);
        g_invC[i] = 1.f / ((float)bse + 1.f);
    }
    __syncthreads();
    int pos = wbase[warp] + excl;
    int* out = g_adj + (size_t)i * NNODE;
    int j0 = tid * 16;
#pragma unroll
    for (int u = 0; u < 16; u++)
        if ((hm >> u) & 1u) out[pos++] = j0 + u;
}

// ---------------- sparse AH gather ----------------
__global__ void __launch_bounds__(128) k_gather() {
    int i = blockIdx.x;
    int deg = g_deg[i], f = threadIdx.x * 4;
    const int* adj = g_adj + (size_t)i * NNODE;
    float4 acc = make_float4(0.f, 0.f, 0.f, 0.f);
    for (int e = 0; e < deg; e++) {
        float4 h = *(const float4*)&g_H[(size_t)adj[e] * LP + f];
        acc.x += h.x; acc.y += h.y; acc.z += h.z; acc.w += h.w;
    }
    *(float4*)&g_AH[(size_t)i * LP + f] = acc;
    float s = g_invS[i];
    *(float4*)&g_AHn[(size_t)i * LP + f] = make_float4(acc.x * s, acc.y * s, acc.z * s, acc.w * s);
}

// ---------------- BatchNorm stats (apply is fused into k_coar) ----------------
__global__ void k_bnsum() {
    int f = threadIdx.x, b = blockIdx.x;
    float s = 0.f, s2 = 0.f;
    for (int n = b; n < NNODE; n += 64) {
        float v = g_Zp[(size_t)n * LP + f];
        s += v; s2 += v * v;
    }
    g_bnp[b * 512 + f] = s; g_bnp2[b * 512 + f] = s2;
}
__global__ void k_bnfin() {
    int f = threadIdx.x;
    float s = 0.f, s2 = 0.f;
    for (int b = 0; b < 64; b++) { s += g_bnp[b * 512 + f]; s2 += g_bnp2[b * 512 + f]; }
    float m = s / (float)NNODE;
    float var = fmaxf(s2 / (float)NNODE - m * m, 0.f);
    g_bnm[f] = m; g_bni[f] = 1.f / sqrtf(var + 1e-5f);
}

// ---------------- ClusterGCN assignment (register-cached rows) ----------------
__global__ void k_cluster(const float* __restrict__ wout, const float* __restrict__ bout,
                          const float* __restrict__ wroot) {
    int warp = threadIdx.x >> 5, lane = threadIdx.x & 31;
    int i = blockIdx.x * 4 + warp;
    float invc = g_invC[i];
    float hv[16], ag[16];
#pragma unroll
    for (int u = 0; u < 16; u++) {
        int k = lane + 32 * u;
        float h = g_H[(size_t)i * LP + k];
        float a = g_AH[(size_t)i * LP + k];
        hv[u] = h; ag[u] = (a + h) * invc;
    }
    float lg[5];
#pragma unroll
    for (int c = 0; c < 5; c++) {
        float acc = 0.f;
#pragma unroll
        for (int u = 0; u < 16; u++) {
            int k = lane + 32 * u;
            if (k < LL) acc += ag[u] * __ldg(&wout[c * LL + k]) + hv[u] * __ldg(&wroot[c * LL + k]);
        }
#pragma unroll
        for (int o = 16; o > 0; o >>= 1) acc += __shfl_down_sync(0xffffffffu, acc, o);
        acc = __shfl_sync(0xffffffffu, acc, 0);
        lg[c] = acc + bout[c];
    }
    if (lane == 0) {
        float m = lg[0];
#pragma unroll
        for (int c = 1; c < 5; c++) m = fmaxf(m, lg[c]);
        float e[5], s = 0.f;
#pragma unroll
        for (int c = 0; c < 5; c++) { e[c] = expf(lg[c] - m); s += e[c]; }
#pragma unroll
        for (int c = 0; c < 5; c++) g_S[(size_t)i * 8 + c] = e[c] / s;
    }
}

// ---------------- T = A @ S via adjacency ----------------
__global__ void __launch_bounds__(256) k_ts() {
    int row = blockIdx.x * 8 + (threadIdx.x >> 5);
    int lane = threadIdx.x & 31;
    int deg = g_deg[row];
    const int* adj = g_adj + (size_t)row * NNODE;
    float a0 = 0.f, a1 = 0.f, a2 = 0.f, a3 = 0.f, a4 = 0.f;
    for (int e = lane; e < deg; e += 32) {
        const float* s = g_S + (size_t)adj[e] * 8;
        a0 += s[0]; a1 += s[1]; a2 += s[2]; a3 += s[3]; a4 += s[4];
    }
#pragma unroll
    for (int o = 16; o > 0; o >>= 1) {
        a0 += __shfl_down_sync(0xffffffffu, a0, o);
        a1 += __shfl_down_sync(0xffffffffu, a1, o);
        a2 += __shfl_down_sync(0xffffffffu, a2, o);
        a3 += __shfl_down_sync(0xffffffffu, a3, o);
        a4 += __shfl_down_sync(0xffffffffu, a4, o);
    }
    if (lane == 0) {
        float* t = g_T + (size_t)row * 8;
        t[0] = a0; t[1] = a1; t[2] = a2; t[3] = a3; t[4] = a4;
    }
}

// ---------------- coar partials = S^T @ BN(Zp) (BN applied inline, exact order) ----------------
__global__ void k_coar(const float* __restrict__ bng, const float* __restrict__ bnb) {
    int fx = threadIdx.x & 63, ny = threadIdx.x >> 6;
    int f = blockIdx.x * 64 + fx, n0 = blockIdx.y * 512;
    float m = g_bnm[f], inv = g_bni[f];
    float gf = (f < LL) ? bng[f] : 0.f;
    float bf = (f < LL) ? bnb[f] : 0.f;
    float acc[5] = {0.f, 0.f, 0.f, 0.f, 0.f};
    for (int n = n0 + ny; n < n0 + 512; n += 4) {
        float v = g_Zp[(size_t)n * LP + f];
        float z = (v - m) * inv * gf + bf;
        const float* s = g_S + (size_t)n * 8;
#pragma unroll
        for (int c = 0; c < 5; c++) acc[c] += s[c] * z;
    }
    __shared__ float red[4][64][5];
#pragma unroll
    for (int c = 0; c < 5; c++) red[ny][fx][c] = acc[c];
    __syncthreads();
    if (ny == 0)
#pragma unroll
        for (int c = 0; c < 5; c++)
            g_cpart[blockIdx.y][c * 512 + f] = red[0][fx][c] + red[1][fx][c] + red[2][fx][c] + red[3][fx][c];
}
__global__ void k_coarfin() {
    int c = blockIdx.x, f = threadIdx.x;
    float s = 0.f;
    for (int b = 0; b < 8; b++) s += g_cpart[b][c * 512 + f];
    g_coar[c * LP + f] = s;
}

// ---------------- Ac = S^T @ T ----------------
__global__ void k_ac() {
    int tid = threadIdx.x, lane = tid & 31, warp = tid >> 5;
    float acc[25];
#pragma unroll
    for (int q = 0; q < 25; q++) acc[q] = 0.f;
    for (int n = tid; n < NNODE; n += 256) {
        float sv[5], tv[5];
#pragma unroll
        for (int c = 0; c < 5; c++) { sv[c] = g_S[(size_t)n * 8 + c]; tv[c] = g_T[(size_t)n * 8 + c]; }
#pragma unroll
        for (int a = 0; a < 5; a++)
#pragma unroll
            for (int b = 0; b < 5; b++) acc[a * 5 + b] += sv[a] * tv[b];
    }
#pragma unroll
    for (int q = 0; q < 25; q++)
#pragma unroll
        for (int o = 16; o > 0; o >>= 1) acc[q] += __shfl_down_sync(0xffffffffu, acc[q], o);
    __shared__ float red[8][25];
    if (lane == 0)
#pragma unroll
        for (int q = 0; q < 25; q++) red[warp][q] = acc[q];
    __syncthreads();
    if (tid < 25) {
        float s = 0.f;
#pragma unroll
        for (int w = 0; w < 8; w++) s += red[w][tid];
        g_Ac[tid] = s;
    }
}

// ---------------- final: coarse SAGE + BN + pool + MLP + softmax ----------------
__global__ void __launch_bounds__(512) k_final(
    const float* __restrict__ wl, const float* __restrict__ bl, const float* __restrict__ wr,
    const float* __restrict__ bng, const float* __restrict__ bnb,
    const float* __restrict__ l1w, const float* __restrict__ l1b,
    const float* __restrict__ l2w, const float* __restrict__ l2b,
    float* __restrict__ out, int out_size) {
    __shared__ float Mc[25], invdc[5], neigh[2500], pre[2500], h1[1250], lg[5];
    int tid = threadIdx.x;
    if (tid == 0) {
        float mean = 0.f;
        for (int q = 0; q < 25; q++) mean += g_Ac[q];
        mean *= (1.f / 25.f);
        for (int q = 0; q < 25; q++) Mc[q] = (g_Ac[q] >= mean && g_Ac[q] > 0.f) ? 1.f : 0.f;
        for (int i = 0; i < 5; i++) {
            float d = 0.f;
            for (int j = 0; j < 5; j++) d += Mc[i * 5 + j];
            invdc[i] = 1.f / fmaxf(d, 1.f);
        }
    }
    __syncthreads();
    for (int idx = tid; idx < 2500; idx += 512) {
        int i = idx / 500, f = idx % 500;
        float a = 0.f;
#pragma unroll
        for (int j = 0; j < 5; j++) a += Mc[i * 5 + j] * g_coar[j * LP + f];
        neigh[idx] = a * invdc[i];
    }
    __syncthreads();
    for (int idx = tid; idx < 2500; idx += 512) {
        int i = idx / 500, f = idx % 500;
        const float* wlr = wl + f * 500;
        const float* wrr = wr + f * 500;
        float a0 = 0.f, a1 = 0.f, a2 = 0.f, a3 = 0.f;
        for (int k = 0; k < 500; k += 4) {
            a0 += neigh[i * 500 + k] * wlr[k] + g_coar[i * LP + k] * wrr[k];
            a1 += neigh[i * 500 + k + 1] * wlr[k + 1] + g_coar[i * LP + k + 1] * wrr[k + 1];
            a2 += neigh[i * 500 + k + 2] * wlr[k + 2] + g_coar[i * LP + k + 2] * wrr[k + 2];
            a3 += neigh[i * 500 + k + 3] * wlr[k + 3] + g_coar[i * LP + k + 3] * wrr[k + 3];
        }
        float acc = bl[f] + ((a0 + a1) + (a2 + a3));
        pre[idx] = (acc >= 0.f) ? acc : 0.01f * acc;
    }
    __syncthreads();
    for (int f = tid; f < 500; f += 512) {
        float m = 0.f;
#pragma unroll
        for (int i = 0; i < 5; i++) m += pre[i * 500 + f];
        m *= 0.2f;
        float v = 0.f;
#pragma unroll
        for (int i = 0; i < 5; i++) { float d = pre[i * 500 + f] - m; v += d * d; }
        v *= 0.2f;
        float sd = sqrtf(v + 1e-5f);
        float gf = bng[f], bf = bnb[f];
#pragma unroll
        for (int i = 0; i < 5; i++) pre[i * 500 + f] = (pre[i * 500 + f] - m) / sd * gf + bf;
    }
    __syncthreads();
    for (int idx = tid; idx < 2500; idx += 512) {
        int i = idx / 500, f = idx % 500;
        float mx = -1e30f;
#pragma unroll
        for (int j = 0; j < 5; j++)
            if (Mc[i * 5 + j] > 0.f || j == i) mx = fmaxf(mx, pre[j * 500 + f]);
        neigh[idx] = mx;
    }
    __syncthreads();
    for (int idx = tid; idx < 1250; idx += 512) {
        int i = idx / 250, o = idx % 250;
        const float* w = l1w + o * 500;
        float a0 = 0.f, a1 = 0.f, a2 = 0.f, a3 = 0.f;
        for (int k = 0; k < 500; k += 4) {
            a0 += neigh[i * 500 + k] * w[k];
            a1 += neigh[i * 500 + k + 1] * w[k + 1];
            a2 += neigh[i * 500 + k + 2] * w[k + 2];
            a3 += neigh[i * 500 + k + 3] * w[k + 3];
        }
        float acc = l1b[o] + ((a0 + a1) + (a2 + a3));
        h1[idx] = (acc >= 0.f) ? acc : 0.01f * acc;
    }
    __syncthreads();
    if (tid < 5) {
        float acc = l2b[0];
        for (int k = 0; k < 250; k++) acc += h1[tid * 250 + k] * l2w[k];
        lg[tid] = (acc >= 0.f) ? acc : 0.01f * acc;
    }
    __syncthreads();
    if (tid == 0) {
        float m = lg[0];
        for (int i = 1; i < 5; i++) m = fmaxf(m, lg[i]);
        float e[5], s = 0.f;
        for (int i = 0; i < 5; i++) { e[i] = expf(lg[i] - m); s += e[i]; }
        float p = 0.f;
        for (int i = 0; i < 5; i++) p = fmaxf(p, e[i] / s);
        out[0] = p;
        if (out_size > 1) out[1] = (p >= 0.5f) ? 1.f : 0.f;
    }
}

// ---------------- host launcher ----------------
static float* symaddr(const void* sym) {
    void* p = nullptr;
    cudaGetSymbolAddress(&p, sym);
    return (float*)p;
}

extern "C" void kernel_launch(void* const* d_in, const int* in_sizes, int n_in,
                              void* d_out, int out_size) {
    const float* x    = (const float*)d_in[0];
    const float* c1w  = (const float*)d_in[1];
    const float* c1b  = (const float*)d_in[2];
    const float* c2w  = (const float*)d_in[3];
    const float* c2b  = (const float*)d_in[4];
    const float* fcw  = (const float*)d_in[5];
    const float* fcb  = (const float*)d_in[6];
    const float* swl  = (const float*)d_in[7];
    const float* sbl  = (const float*)d_in[8];
    const float* swr  = (const float*)d_in[9];
    const float* bng  = (const float*)d_in[10];
    const float* bnb  = (const float*)d_in[11];
    const float* cgwo = (const float*)d_in[12];
    const float* cgbo = (const float*)d_in[13];
    const float* cgwr = (const float*)d_in[14];
    const float* l1w  = (const float*)d_in[15];
    const float* l1b  = (const float*)d_in[16];
    const float* l2w  = (const float*)d_in[17];
    const float* l2b  = (const float*)d_in[18];
    float* out = (float*)d_out;

    float* pF   = symaddr(g_F);
    float* pH   = symaddr(g_H);
    float* pAHn = symaddr(g_AHn);
    float* pZp  = symaddr(g_Zp);
    float* pW   = symaddr(g_W);

    const int c2_smem = C2_IMGS * 3840 * (int)sizeof(float);
    cudaFuncSetAttribute(k_conv2, cudaFuncAttributeMaxDynamicSharedMemorySize, c2_smem);

    k_zero<<<1, 64>>>();
    k_packw<<<512, 256>>>(swl, swr);
    k_packc2<<<25, 256>>>(c2w);
    k_conv1<<<NNODE, 384>>>(x, c1w, c1b);
    k_conv2<<<(NNODE + C2_IMGS - 1) / C2_IMGS, 512, c2_smem>>>(c2b);
    {   // fc: H = relu(F @ fcw^T + fcb), split-K 2 (400+400); fused row norms
        dim3 g(4, 32, 2);
        k_gemm_sk<<<g, 256>>>(pF, pF + 400, FEAT, fcw, fcw + 400, FEAT, 400, LL);
        k_comb<<<NNODE, 128>>>(fcb, pH, 1, 1);
    }
    k_gram<<<528, 256>>>();
    k_thr<<<1, 1>>>();
    k_adj<<<NNODE, 256>>>();
    k_gather<<<NNODE, 128>>>();
    {   // SAGE: Zp = leaky(AHn@wl^T + H@wr^T + bl), two slots of packed W
        dim3 g(4, 32, 2);
        k_gemm_sk<<<g, 256>>>(pAHn, pH, LP, pW, pW + 512, 1024, 512, LP);
        k_comb<<<NNODE, 128>>>(sbl, pZp, 2, 0);
    }
    k_bnsum<<<64, 512>>>();
    k_bnfin<<<1, 512>>>();
    k_cluster<<<NNODE / 4, 128>>>(cgwo, cgbo, cgwr);
    k_ts<<<NNODE / 8, 256>>>();
    {
        dim3 g(8, 8);
        k_coar<<<g, 256>>>(bng, bnb);
        k_coarfin<<<5, 512>>>();
    }
    k_ac<<<1, 256>>>();
    k_final<<<1, 512>>>(swl, sbl, swr, bng, bnb, l1w, l1b, l2w, l2b, out, out_size);
}

// round 16
// speedup vs baseline: 1.0398x; 1.0147x over previous
#include <cuda_runtime.h>
#include <math.h>

#define NNODE 4096
#define LL 500
#define LP 512
#define FEAT 800

typedef unsigned long long ull;

// ---------------- scratch (device globals; no allocation) ----------------
__device__ float g_P1[NNODE * 3840];
__device__ float g_F[NNODE * FEAT];
__device__ float g_H[NNODE * LP];
__device__ float g_sq[NNODE];
__device__ unsigned char g_bin[(size_t)NNODE * NNODE];
__device__ unsigned int g_hist[64];
__device__ int   g_kthr;
__device__ int   g_adj[(size_t)NNODE * NNODE];
__device__ int   g_deg[NNODE];
__device__ float g_invS[NNODE];
__device__ float g_invC[NNODE];
__device__ float g_AH[NNODE * LP];
__device__ float g_AHn[NNODE * LP];
__device__ float g_W[512 * 1024];
__device__ ull   g_c2w[25 * 20 * 25];          // packed conv2 weights [cp][ic][tap]
__device__ ull   g_c1w[10 * 25];               // packed conv1 weights [cp][tap]
__device__ float g_part0[(size_t)NNODE * LP];
__device__ float g_part1[(size_t)NNODE * LP];
__device__ float g_Zp[NNODE * LP];
__device__ float g_S[NNODE * 8];
__device__ float g_T[NNODE * 8];
__device__ float g_cpart[8][5 * 512];
__device__ float g_coar[5 * LP];
__device__ float g_Ac[25];
__device__ float g_bnp[64 * 512];
__device__ float g_bnp2[64 * 512];
__device__ float g_bnm[512];
__device__ float g_bni[512];

__global__ void k_zero() { if (threadIdx.x < 64) g_hist[threadIdx.x] = 0u; }

// ---------------- packed fp32x2 helpers ----------------
__device__ __forceinline__ void fma2(ull &d, ull a, ull b) {
    asm("fma.rn.f32x2 %0, %1, %2, %0;" : "+l"(d) : "l"(a), "l"(b));
}
__device__ __forceinline__ ull pk2(float a, float b) {
    ull r; asm("mov.b64 %0, {%1, %2};" : "=l"(r) : "f"(a), "f"(b)); return r;
}
__device__ __forceinline__ ull dup2(float a) { return pk2(a, a); }
__device__ __forceinline__ float2 up2(ull v) {
    float2 r; r.x = __uint_as_float((unsigned)v); r.y = __uint_as_float((unsigned)(v >> 32)); return r;
}

// compute core: 128x128 tile, BK=16, plain A (packed after load), acc 8 rows x 4 col-pairs
__device__ __forceinline__ void gemm_core_p(const float (*As)[128], const float (*Bs)[128],
                                            int tx, int ty, ull acc[8][4]) {
#pragma unroll
    for (int kk = 0; kk < 16; kk++) {
        float4 a0 = *(const float4*)&As[kk][4 * ty];
        float4 a1 = *(const float4*)&As[kk][4 * ty + 64];
        ulonglong2 B01 = *(const ulonglong2*)&Bs[kk][4 * tx];
        ulonglong2 B23 = *(const ulonglong2*)&Bs[kk][4 * tx + 64];
        ull av[8] = {dup2(a0.x), dup2(a0.y), dup2(a0.z), dup2(a0.w),
                     dup2(a1.x), dup2(a1.y), dup2(a1.z), dup2(a1.w)};
        ull bv[4] = {B01.x, B01.y, B23.x, B23.y};
#pragma unroll
        for (int i = 0; i < 8; i++)
#pragma unroll
            for (int j = 0; j < 4; j++) fma2(acc[i][j], av[i], bv[j]);
    }
}

// ---------------- pack conv weights into channel pairs ----------------
__global__ void k_packc2(const float* __restrict__ w) {
    int cp = blockIdx.x;                 // 0..24
    for (int i = threadIdx.x; i < 500; i += 256)   // ic*25 + tap
        g_c2w[cp * 500 + i] = pk2(w[(2 * cp) * 500 + i], w[(2 * cp + 1) * 500 + i]);
}
__global__ void k_packc1(const float* __restrict__ w) {
    int i = threadIdx.x;                 // cp*25 + tap, 250 total
    if (i < 250) {
        int cp = i / 25, tap = i % 25;
        g_c1w[i] = pk2(w[(2 * cp) * 25 + tap], w[(2 * cp + 1) * 25 + tap]);
    }
}

// ---------------- conv1 (1->20,5x5)+relu+pool, channel-paired f32x2, packed weights ----------------
__global__ void __launch_bounds__(384) k_conv1(const float* __restrict__ x,
                                               const float* __restrict__ b) {
    int n = blockIdx.x;
    __shared__ __align__(16) float simg[784];
    const float* xi = x + (size_t)n * 784;
    for (int i = threadIdx.x; i < 784; i += 384) simg[i] = xi[i];
    __syncthreads();
    int t = threadIdx.x;
    if (t >= 360) return;
    int p = t / 36, reg = t % 36, c0 = p * 2;
    int ry = (reg / 6) * 2, rx = (reg % 6) * 2;
    ull wp[25];
    const ull* pw = g_c1w + p * 25;
#pragma unroll
    for (int u = 0; u < 25; u++) wp[u] = __ldg(pw + u);
    ull a2[4][4];
#pragma unroll
    for (int i = 0; i < 4; i++)
#pragma unroll
        for (int j = 0; j < 4; j++) a2[i][j] = 0ULL;
#pragma unroll
    for (int rr = 0; rr < 8; rr++) {
        const float* sp = simg + (2 * ry + rr) * 28 + 2 * rx;
        float4 q0 = *(const float4*)sp;
        float4 q1 = *(const float4*)(sp + 4);
        ull rd[8] = {dup2(q0.x), dup2(q0.y), dup2(q0.z), dup2(q0.w),
                     dup2(q1.x), dup2(q1.y), dup2(q1.z), dup2(q1.w)};
        int iy0 = rr - 4 > 0 ? rr - 4 : 0, iy1 = rr < 3 ? rr : 3;
#pragma unroll 4
        for (int iy = iy0; iy <= iy1; iy++) {
            int ky = rr - iy;
#pragma unroll
            for (int ix = 0; ix < 4; ix++)
#pragma unroll
                for (int kx = 0; kx < 5; kx++) fma2(a2[iy][ix], rd[ix + kx], wp[ky * 5 + kx]);
        }
    }
    float b0 = b[c0], b1 = b[c0 + 1];
#pragma unroll
    for (int py = 0; py < 2; py++)
#pragma unroll
        for (int px = 0; px < 2; px++) {
            float2 v00 = up2(a2[2 * py][2 * px]), v01 = up2(a2[2 * py][2 * px + 1]);
            float2 v10 = up2(a2[2 * py + 1][2 * px]), v11 = up2(a2[2 * py + 1][2 * px + 1]);
            float m0 = fmaxf(fmaxf(v00.x, v01.x), fmaxf(v10.x, v11.x));
            float m1 = fmaxf(fmaxf(v00.y, v01.y), fmaxf(v10.y, v11.y));
            int yy = ry + py, xx = rx + px;
            g_P1[(size_t)n * 3840 + c0 * 192 + yy * 16 + xx] = fmaxf(m0 + b0, 0.f);
            g_P1[(size_t)n * 3840 + (c0 + 1) * 192 + yy * 16 + xx] = fmaxf(m1 + b1, 0.f);
        }
}

// ---------------- conv2: 5 images/block, channel-paired f32x2, packed weights ----------------
#define C2_IMGS 5
__global__ void __launch_bounds__(512, 1) k_conv2(const float* __restrict__ b) {
    extern __shared__ __align__(16) float sp5[];
    int n0 = blockIdx.x * C2_IMGS;
    for (int v = threadIdx.x; v < 960 * C2_IMGS; v += 512) {
        int img = v / 960, idx = v % 960;
        if (n0 + img < NNODE)
            ((float4*)(sp5 + img * 3840))[idx] = ((const float4*)(g_P1 + (size_t)(n0 + img) * 3840))[idx];
    }
    __syncthreads();
    int t = threadIdx.x;
    if (t >= 100 * C2_IMGS) return;
    int img = t / 100, t2 = t % 100, n = n0 + img;
    if (n >= NNODE) return;
    int cp = t2 >> 2, q = t2 & 3, c0 = cp * 2;
    int ry = (q >> 1) * 2, rx = (q & 1) * 2;
    ull a2[4][4];
#pragma unroll
    for (int i = 0; i < 4; i++)
#pragma unroll
        for (int j = 0; j < 4; j++) a2[i][j] = 0ULL;
    const float* sp = sp5 + img * 3840;
    const ull* pw = g_c2w + cp * 500;
    for (int ic = 0; ic < 20; ic++) {
        ull wp[25];
        const ull* w0 = pw + ic * 25;
#pragma unroll
        for (int u = 0; u < 25; u++) wp[u] = __ldg(w0 + u);
#pragma unroll
        for (int rr = 0; rr < 8; rr++) {
            const float* rp = sp + ic * 192 + (2 * ry + rr) * 16 + 2 * rx;
            float4 q0 = *(const float4*)rp;
            float4 q1 = *(const float4*)(rp + 4);
            ull rd[8] = {dup2(q0.x), dup2(q0.y), dup2(q0.z), dup2(q0.w),
                         dup2(q1.x), dup2(q1.y), dup2(q1.z), dup2(q1.w)};
            int iy0 = rr - 4 > 0 ? rr - 4 : 0, iy1 = rr < 3 ? rr : 3;
#pragma unroll 4
            for (int iy = iy0; iy <= iy1; iy++) {
                int ky = rr - iy;
#pragma unroll
                for (int ix = 0; ix < 4; ix++)
#pragma unroll
                    for (int kx = 0; kx < 5; kx++) fma2(a2[iy][ix], rd[ix + kx], wp[ky * 5 + kx]);
            }
        }
    }
    float b0 = b[c0], b1 = b[c0 + 1];
#pragma unroll
    for (int py = 0; py < 2; py++)
#pragma unroll
        for (int px = 0; px < 2; px++) {
            float2 v00 = up2(a2[2 * py][2 * px]), v01 = up2(a2[2 * py][2 * px + 1]);
            float2 v10 = up2(a2[2 * py + 1][2 * px]), v11 = up2(a2[2 * py + 1][2 * px + 1]);
            float m0 = fmaxf(fmaxf(v00.x, v01.x), fmaxf(v10.x, v11.x));
            float m1 = fmaxf(fmaxf(v00.y, v01.y), fmaxf(v10.y, v11.y));
            g_F[(size_t)n * 800 + c0 * 16 + (ry + py) * 4 + rx + px] = fmaxf(m0 + b0, 0.f);
            g_F[(size_t)n * 800 + (c0 + 1) * 16 + (ry + py) * 4 + rx + px] = fmaxf(m1 + b1, 0.f);
        }
}

// ---------------- split NT GEMM: z slot picks (A,B) pair, raw partial out ----------------
__global__ void __launch_bounds__(256, 2) k_gemm_sk(
    const float* __restrict__ A0, const float* __restrict__ A1, int lda,
    const float* __restrict__ B0, const float* __restrict__ B1, int ldb,
    int K, int Nc) {
    __shared__ float As[16][128];
    __shared__ float Bs[16][128];
    int tid = threadIdx.x, tx = tid & 15, ty = tid >> 4;
    int zz = blockIdx.z;
    const float* A = zz ? A1 : A0;
    const float* B = zz ? B1 : B0;
    float* Cp = zz ? g_part1 : g_part0;
    int brow = blockIdx.y * 128, bcol = blockIdx.x * 128;
    int lrow = tid >> 1, lk = (tid & 1) * 8;
    int gr = brow + lrow, gc = bcol + lrow;
    int bok = (gc < Nc);
    ull acc[8][4];
#pragma unroll
    for (int i = 0; i < 8; i++)
#pragma unroll
        for (int j = 0; j < 4; j++) acc[i][j] = 0ULL;
    const float4 z4 = make_float4(0.f, 0.f, 0.f, 0.f);
    float4 ra0, ra1, rb0, rb1;
    ra0 = *(const float4*)(A + (size_t)gr * lda + lk);
    ra1 = *(const float4*)(A + (size_t)gr * lda + lk + 4);
    rb0 = bok ? *(const float4*)(B + (size_t)gc * ldb + lk) : z4;
    rb1 = bok ? *(const float4*)(B + (size_t)gc * ldb + lk + 4) : z4;
    int ktiles = K >> 4;
    for (int tt = 0; tt < ktiles; tt++) {
        __syncthreads();
        const float* pa0 = (const float*)&ra0;
        const float* pa1 = (const float*)&ra1;
        const float* pb0 = (const float*)&rb0;
        const float* pb1 = (const float*)&rb1;
#pragma unroll
        for (int j = 0; j < 4; j++) {
            As[lk + j][lrow] = pa0[j];
            As[lk + 4 + j][lrow] = pa1[j];
            Bs[lk + j][lrow] = pb0[j];
            Bs[lk + 4 + j][lrow] = pb1[j];
        }
        __syncthreads();
        if (tt + 1 < ktiles) {
            int kb = (tt + 1) * 16 + lk;
            ra0 = *(const float4*)(A + (size_t)gr * lda + kb);
            ra1 = *(const float4*)(A + (size_t)gr * lda + kb + 4);
            rb0 = bok ? *(const float4*)(B + (size_t)gc * ldb + kb) : z4;
            rb1 = bok ? *(const float4*)(B + (size_t)gc * ldb + kb + 4) : z4;
        }
        gemm_core_p(As, Bs, tx, ty, acc);
    }
#pragma unroll
    for (int i = 0; i < 8; i++) {
        int r = brow + ty * 4 + (i & 3) + ((i >> 2) << 6);
#pragma unroll
        for (int j = 0; j < 4; j++) {
            int c = bcol + tx * 4 + ((j & 1) << 1) + ((j >> 1) << 6);
            float2 v = up2(acc[i][j]);
            Cp[(size_t)r * LP + c] = v.x;
            Cp[(size_t)r * LP + c + 1] = v.y;
        }
    }
}

// ---------------- combine split parts + bias + act (+ optional row norm) ----------------
__global__ void k_comb(const float* __restrict__ bias, float* __restrict__ dst,
                       int act, int rn) {
    int i = blockIdx.x;
    int tid = threadIdx.x;
    int c = tid * 4;
    float4 o = make_float4(0.f, 0.f, 0.f, 0.f);
    if (c < LL) {
        float4 v0 = *(const float4*)&g_part0[(size_t)i * LP + c];
        float4 v1 = *(const float4*)&g_part1[(size_t)i * LP + c];
        o.x = v0.x + v1.x + bias[c];
        o.y = v0.y + v1.y + bias[c + 1];
        o.z = v0.z + v1.z + bias[c + 2];
        o.w = v0.w + v1.w + bias[c + 3];
        if (act == 1) {
            o.x = fmaxf(o.x, 0.f); o.y = fmaxf(o.y, 0.f);
            o.z = fmaxf(o.z, 0.f); o.w = fmaxf(o.w, 0.f);
        } else {
            o.x = o.x >= 0.f ? o.x : 0.01f * o.x;
            o.y = o.y >= 0.f ? o.y : 0.01f * o.y;
            o.z = o.z >= 0.f ? o.z : 0.01f * o.z;
            o.w = o.w >= 0.f ? o.w : 0.01f * o.w;
        }
    }
    *(float4*)&dst[(size_t)i * LP + c] = o;
    if (rn) {
        float s = o.x * o.x + o.y * o.y + o.z * o.z + o.w * o.w;
        int lane = tid & 31, warp = tid >> 5;
#pragma unroll
        for (int off = 16; off > 0; off >>= 1) s += __shfl_down_sync(0xffffffffu, s, off);
        __shared__ float red[4];
        if (lane == 0) red[warp] = s;
        __syncthreads();
        if (tid == 0) g_sq[i] = red[0] + red[1] + red[2] + red[3];
    }
}

// ---------------- pack [wl | wr] into g_W [512][1024] ----------------
__global__ void k_packw(const float* __restrict__ wl, const float* __restrict__ wr) {
    int n = blockIdx.x;
    for (int k = threadIdx.x; k < 1024; k += 256) {
        float v = 0.f;
        if (n < LL) {
            if (k < LL) v = wl[n * LL + k];
            else if (k >= 512 && k < 512 + LL) v = wr[n * LL + (k - 512)];
        }
        g_W[n * 1024 + k] = v;
    }
}

// ---------------- triangular Gram -> bins (smem-staged coalesced) + histogram ----------------
__global__ void __launch_bounds__(256, 2) k_gram() {
    __shared__ float As[16][128];
    __shared__ float Bs[16][128];
    __shared__ unsigned int shist[64];
    __shared__ unsigned char sbin[128][132];
    int tid = threadIdx.x, tx = tid & 15, ty = tid >> 4;
    if (tid < 64) shist[tid] = 0u;
    int bid = blockIdx.x, by = 0, rem = bid;
    while (rem >= 32 - by) { rem -= 32 - by; by++; }
    int bx = by + rem;
    int brow = by * 128, bcol = bx * 128;
    int lrow = tid >> 1, lk = (tid & 1) * 8;
    int gr = brow + lrow, gc = bcol + lrow;
    ull acc[8][4];
#pragma unroll
    for (int i = 0; i < 8; i++)
#pragma unroll
        for (int j = 0; j < 4; j++) acc[i][j] = 0ULL;
    float4 ra0, ra1, rb0, rb1;
    ra0 = *(const float4*)(g_H + (size_t)gr * LP + lk);
    ra1 = *(const float4*)(g_H + (size_t)gr * LP + lk + 4);
    rb0 = *(const float4*)(g_H + (size_t)gc * LP + lk);
    rb1 = *(const float4*)(g_H + (size_t)gc * LP + lk + 4);
    for (int tt = 0; tt < 32; tt++) {
        __syncthreads();
        const float* pa0 = (const float*)&ra0;
        const float* pa1 = (const float*)&ra1;
        const float* pb0 = (const float*)&rb0;
        const float* pb1 = (const float*)&rb1;
#pragma unroll
        for (int j = 0; j < 4; j++) {
            As[lk + j][lrow] = pa0[j];
            As[lk + 4 + j][lrow] = pa1[j];
            Bs[lk + j][lrow] = pb0[j];
            Bs[lk + 4 + j][lrow] = pb1[j];
        }
        __syncthreads();
        if (tt + 1 < 32) {
            int kb = (tt + 1) * 16 + lk;
            ra0 = *(const float4*)(g_H + (size_t)gr * LP + kb);
            ra1 = *(const float4*)(g_H + (size_t)gr * LP + kb + 4);
            rb0 = *(const float4*)(g_H + (size_t)gc * LP + kb);
            rb1 = *(const float4*)(g_H + (size_t)gc * LP + kb + 4);
        }
        gemm_core_p(As, Bs, tx, ty, acc);
    }
    float sqr_[8], sqc_[8];
#pragma unroll
    for (int i = 0; i < 8; i++) sqr_[i] = g_sq[brow + ty * 4 + (i & 3) + ((i >> 2) << 6)];
#pragma unroll
    for (int j = 0; j < 8; j++) sqc_[j] = g_sq[bcol + tx * 4 + (j & 3) + ((j >> 2) << 6)];
    unsigned wgt = (bx == by) ? 1u : 2u;
#pragma unroll
    for (int i = 0; i < 8; i++) {
        int lr = ty * 4 + (i & 3) + ((i >> 2) << 6);
        int r = brow + lr;
#pragma unroll
        for (int j = 0; j < 4; j++) {
            int lcb = tx * 4 + ((j & 1) << 1) + ((j >> 1) << 6);
            float2 v = up2(acc[i][j]);
#pragma unroll
            for (int e = 0; e < 2; e++) {
                int lc = lcb + e;
                int c = bcol + lc;
                int ce = ((j >> 1) << 2) + ((j & 1) << 1) + e;
                float dot = e ? v.y : v.x;
                float d2 = fmaxf(sqr_[i] - 2.f * dot + sqc_[ce], 0.f);
                int bin;
                if (r == c) bin = 255;
                else if (d2 < 6.25f) bin = 0;
                else {
                    float d = sqrtf(d2);
                    bin = 1 + (int)((d - 2.5f) * 2.0f);
                    if (bin > 63) bin = 63;
                    float t = 2.5f + 0.5f * (float)bin;
                    if (!(d2 < t * t)) { bin++; if (bin > 63) bin = 63; }
                    else if (bin > 1) { float tm = t - 0.5f; if (d2 < tm * tm) bin--; }
                }
                sbin[lr][lc] = (unsigned char)bin;
                unsigned msk = __match_any_sync(0xffffffffu, bin);
                int leader = __ffs(msk) - 1;
                if ((int)(tid & 31) == leader && bin < 64)
                    atomicAdd(&shist[bin], (unsigned)__popc(msk) * wgt);
            }
        }
    }
    __syncthreads();
    if (tid < 64 && shist[tid]) atomicAdd(&g_hist[tid], shist[tid]);
    for (int idx = tid; idx < 1024; idx += 256) {
        int row = idx >> 3, cq = (idx & 7) * 16;
        union { unsigned char b[16]; uint4 v; } u;
#pragma unroll
        for (int k = 0; k < 16; k++) u.b[k] = sbin[row][cq + k];
        *(uint4*)&g_bin[(size_t)(brow + row) * NNODE + bcol + cq] = u.v;
    }
    if (bx != by) {
        for (int idx = tid; idx < 1024; idx += 256) {
            int row = idx >> 3, cq = (idx & 7) * 16;
            union { unsigned char b[16]; uint4 v; } u;
#pragma unroll
            for (int k = 0; k < 16; k++) u.b[k] = sbin[cq + k][row];
            *(uint4*)&g_bin[(size_t)(bcol + row) * NNODE + brow + cq] = u.v;
        }
    }
}

// ---------------- pick threshold bin ----------------
__global__ void k_thr() {
    unsigned cum = 0; int k = 0;
    for (k = 0; k < 64; k++) { cum += g_hist[k]; if ((float)cum >= 409.6f) break; }
    if (k > 63) k = 63;
    g_kthr = k;
}

// ---------------- adjacency build ----------------
__global__ void __launch_bounds__(256) k_adj() {
    int i = blockIdx.x;
    int tid = threadIdx.x, lane = tid & 31, warp = tid >> 5;
    int kthr = g_kthr;
    uint4 v = ((const uint4*)(g_bin + (size_t)i * NNODE))[tid];
    unsigned words[4] = {v.x, v.y, v.z, v.w};
    int cnt = 0; unsigned hm = 0;
#pragma unroll
    for (int wq = 0; wq < 4; wq++)
#pragma unroll
        for (int bq = 0; bq < 4; bq++) {
            int bv = (int)((words[wq] >> (bq * 8)) & 0xffu);
            bool h = (bv <= kthr);
            cnt += h ? 1 : 0;
            hm |= (h ? 1u : 0u) << (wq * 4 + bq);
        }
    int sc = cnt;
#pragma unroll
    for (int o = 1; o < 32; o <<= 1) {
        int t2 = __shfl_up_sync(0xffffffffu, sc, o);
        if (lane >= o) sc += t2;
    }
    __shared__ int wtot[8], wbase[8];
    if (lane == 31) wtot[warp] = sc;
    int excl = sc - cnt;
    __syncthreads();
    if (tid == 0) {
        int bse = 0;
        for (int w = 0; w < 8; w++) { wbase[w] = bse; bse += wtot[w]; }
        g_deg[i] = bse;
        g_invS[i] = 1.f / fmaxf((float)bse, 1.f);
        g_invC[i] = 1.f / ((float)bse + 1.f);
    }
    __syncthreads();
    int pos = wbase[warp] + excl;
    int* out = g_adj + (size_t)i * NNODE;
    int j0 = tid * 16;
#pragma unroll
    for (int u = 0; u < 16; u++)
        if ((hm >> u) & 1u) out[pos++] = j0 + u;
}

// ---------------- sparse AH gather ----------------
__global__ void __launch_bounds__(128) k_gather() {
    int i = blockIdx.x;
    int deg = g_deg[i], f = threadIdx.x * 4;
    const int* adj = g_adj + (size_t)i * NNODE;
    float4 acc = make_float4(0.f, 0.f, 0.f, 0.f);
    for (int e = 0; e < deg; e++) {
        float4 h = *(const float4*)&g_H[(size_t)adj[e] * LP + f];
        acc.x += h.x; acc.y += h.y; acc.z += h.z; acc.w += h.w;
    }
    *(float4*)&g_AH[(size_t)i * LP + f] = acc;
    float s = g_invS[i];
    *(float4*)&g_AHn[(size_t)i * LP + f] = make_float4(acc.x * s, acc.y * s, acc.z * s, acc.w * s);
}

// ---------------- BatchNorm stats (apply is fused into k_coar) ----------------
__global__ void k_bnsum() {
    int f = threadIdx.x, b = blockIdx.x;
    float s = 0.f, s2 = 0.f;
    for (int n = b; n < NNODE; n += 64) {
        float v = g_Zp[(size_t)n * LP + f];
        s += v; s2 += v * v;
    }
    g_bnp[b * 512 + f] = s; g_bnp2[b * 512 + f] = s2;
}
__global__ void k_bnfin() {
    int f = threadIdx.x;
    float s = 0.f, s2 = 0.f;
    for (int b = 0; b < 64; b++) { s += g_bnp[b * 512 + f]; s2 += g_bnp2[b * 512 + f]; }
    float m = s / (float)NNODE;
    float var = fmaxf(s2 / (float)NNODE - m * m, 0.f);
    g_bnm[f] = m; g_bni[f] = 1.f / sqrtf(var + 1e-5f);
}

// ---------------- ClusterGCN assignment (register-cached rows) ----------------
__global__ void k_cluster(const float* __restrict__ wout, const float* __restrict__ bout,
                          const float* __restrict__ wroot) {
    int warp = threadIdx.x >> 5, lane = threadIdx.x & 31;
    int i = blockIdx.x * 4 + warp;
    float invc = g_invC[i];
    float hv[16], ag[16];
#pragma unroll
    for (int u = 0; u < 16; u++) {
        int k = lane + 32 * u;
        float h = g_H[(size_t)i * LP + k];
        float a = g_AH[(size_t)i * LP + k];
        hv[u] = h; ag[u] = (a + h) * invc;
    }
    float lg[5];
#pragma unroll
    for (int c = 0; c < 5; c++) {
        float acc = 0.f;
#pragma unroll
        for (int u = 0; u < 16; u++) {
            int k = lane + 32 * u;
            if (k < LL) acc += ag[u] * __ldg(&wout[c * LL + k]) + hv[u] * __ldg(&wroot[c * LL + k]);
        }
#pragma unroll
        for (int o = 16; o > 0; o >>= 1) acc += __shfl_down_sync(0xffffffffu, acc, o);
        acc = __shfl_sync(0xffffffffu, acc, 0);
        lg[c] = acc + bout[c];
    }
    if (lane == 0) {
        float m = lg[0];
#pragma unroll
        for (int c = 1; c < 5; c++) m = fmaxf(m, lg[c]);
        float e[5], s = 0.f;
#pragma unroll
        for (int c = 0; c < 5; c++) { e[c] = expf(lg[c] - m); s += e[c]; }
#pragma unroll
        for (int c = 0; c < 5; c++) g_S[(size_t)i * 8 + c] = e[c] / s;
    }
}

// ---------------- T = A @ S via adjacency ----------------
__global__ void __launch_bounds__(256) k_ts() {
    int row = blockIdx.x * 8 + (threadIdx.x >> 5);
    int lane = threadIdx.x & 31;
    int deg = g_deg[row];
    const int* adj = g_adj + (size_t)row * NNODE;
    float a0 = 0.f, a1 = 0.f, a2 = 0.f, a3 = 0.f, a4 = 0.f;
    for (int e = lane; e < deg; e += 32) {
        const float* s = g_S + (size_t)adj[e] * 8;
        a0 += s[0]; a1 += s[1]; a2 += s[2]; a3 += s[3]; a4 += s[4];
    }
#pragma unroll
    for (int o = 16; o > 0; o >>= 1) {
        a0 += __shfl_down_sync(0xffffffffu, a0, o);
        a1 += __shfl_down_sync(0xffffffffu, a1, o);
        a2 += __shfl_down_sync(0xffffffffu, a2, o);
        a3 += __shfl_down_sync(0xffffffffu, a3, o);
        a4 += __shfl_down_sync(0xffffffffu, a4, o);
    }
    if (lane == 0) {
        float* t = g_T + (size_t)row * 8;
        t[0] = a0; t[1] = a1; t[2] = a2; t[3] = a3; t[4] = a4;
    }
}

// ---------------- coar partials = S^T @ BN(Zp) (BN applied inline, exact order) ----------------
__global__ void k_coar(const float* __restrict__ bng, const float* __restrict__ bnb) {
    int fx = threadIdx.x & 63, ny = threadIdx.x >> 6;
    int f = blockIdx.x * 64 + fx, n0 = blockIdx.y * 512;
    float m = g_bnm[f], inv = g_bni[f];
    float gf = (f < LL) ? bng[f] : 0.f;
    float bf = (f < LL) ? bnb[f] : 0.f;
    float acc[5] = {0.f, 0.f, 0.f, 0.f, 0.f};
    for (int n = n0 + ny; n < n0 + 512; n += 4) {
        float v = g_Zp[(size_t)n * LP + f];
        float z = (v - m) * inv * gf + bf;
        const float* s = g_S + (size_t)n * 8;
#pragma unroll
        for (int c = 0; c < 5; c++) acc[c] += s[c] * z;
    }
    __shared__ float red[4][64][5];
#pragma unroll
    for (int c = 0; c < 5; c++) red[ny][fx][c] = acc[c];
    __syncthreads();
    if (ny == 0)
#pragma unroll
        for (int c = 0; c < 5; c++)
            g_cpart[blockIdx.y][c * 512 + f] = red[0][fx][c] + red[1][fx][c] + red[2][fx][c] + red[3][fx][c];
}
__global__ void k_coarfin() {
    int c = blockIdx.x, f = threadIdx.x;
    float s = 0.f;
    for (int b = 0; b < 8; b++) s += g_cpart[b][c * 512 + f];
    g_coar[c * LP + f] = s;
}

// ---------------- Ac = S^T @ T ----------------
__global__ void k_ac() {
    int tid = threadIdx.x, lane = tid & 31, warp = tid >> 5;
    float acc[25];
#pragma unroll
    for (int q = 0; q < 25; q++) acc[q] = 0.f;
    for (int n = tid; n < NNODE; n += 256) {
        float sv[5], tv[5];
#pragma unroll
        for (int c = 0; c < 5; c++) { sv[c] = g_S[(size_t)n * 8 + c]; tv[c] = g_T[(size_t)n * 8 + c]; }
#pragma unroll
        for (int a = 0; a < 5; a++)
#pragma unroll
            for (int b = 0; b < 5; b++) acc[a * 5 + b] += sv[a] * tv[b];
    }
#pragma unroll
    for (int q = 0; q < 25; q++)
#pragma unroll
        for (int o = 16; o > 0; o >>= 1) acc[q] += __shfl_down_sync(0xffffffffu, acc[q], o);
    __shared__ float red[8][25];
    if (lane == 0)
#pragma unroll
        for (int q = 0; q < 25; q++) red[warp][q] = acc[q];
    __syncthreads();
    if (tid < 25) {
        float s = 0.f;
#pragma unroll
        for (int w = 0; w < 8; w++) s += red[w][tid];
        g_Ac[tid] = s;
    }
}

// ---------------- final: coarse SAGE + BN + pool + MLP + softmax ----------------
__global__ void __launch_bounds__(512) k_final(
    const float* __restrict__ wl, const float* __restrict__ bl, const float* __restrict__ wr,
    const float* __restrict__ bng, const float* __restrict__ bnb,
    const float* __restrict__ l1w, const float* __restrict__ l1b,
    const float* __restrict__ l2w, const float* __restrict__ l2b,
    float* __restrict__ out, int out_size) {
    __shared__ float Mc[25], invdc[5], neigh[2500], pre[2500], h1[1250], lg[5];
    int tid = threadIdx.x;
    if (tid == 0) {
        float mean = 0.f;
        for (int q = 0; q < 25; q++) mean += g_Ac[q];
        mean *= (1.f / 25.f);
        for (int q = 0; q < 25; q++) Mc[q] = (g_Ac[q] >= mean && g_Ac[q] > 0.f) ? 1.f : 0.f;
        for (int i = 0; i < 5; i++) {
            float d = 0.f;
            for (int j = 0; j < 5; j++) d += Mc[i * 5 + j];
            invdc[i] = 1.f / fmaxf(d, 1.f);
        }
    }
    __syncthreads();
    for (int idx = tid; idx < 2500; idx += 512) {
        int i = idx / 500, f = idx % 500;
        float a = 0.f;
#pragma unroll
        for (int j = 0; j < 5; j++) a += Mc[i * 5 + j] * g_coar[j * LP + f];
        neigh[idx] = a * invdc[i];
    }
    __syncthreads();
    for (int idx = tid; idx < 2500; idx += 512) {
        int i = idx / 500, f = idx % 500;
        const float* wlr = wl + f * 500;
        const float* wrr = wr + f * 500;
        float a0 = 0.f, a1 = 0.f, a2 = 0.f, a3 = 0.f;
        for (int k = 0; k < 500; k += 4) {
            a0 += neigh[i * 500 + k] * wlr[k] + g_coar[i * LP + k] * wrr[k];
            a1 += neigh[i * 500 + k + 1] * wlr[k + 1] + g_coar[i * LP + k + 1] * wrr[k + 1];
            a2 += neigh[i * 500 + k + 2] * wlr[k + 2] + g_coar[i * LP + k + 2] * wrr[k + 2];
            a3 += neigh[i * 500 + k + 3] * wlr[k + 3] + g_coar[i * LP + k + 3] * wrr[k + 3];
        }
        float acc = bl[f] + ((a0 + a1) + (a2 + a3));
        pre[idx] = (acc >= 0.f) ? acc : 0.01f * acc;
    }
    __syncthreads();
    for (int f = tid; f < 500; f += 512) {
        float m = 0.f;
#pragma unroll
        for (int i = 0; i < 5; i++) m += pre[i * 500 + f];
        m *= 0.2f;
        float v = 0.f;
#pragma unroll
        for (int i = 0; i < 5; i++) { float d = pre[i * 500 + f] - m; v += d * d; }
        v *= 0.2f;
        float sd = sqrtf(v + 1e-5f);
        float gf = bng[f], bf = bnb[f];
#pragma unroll
        for (int i = 0; i < 5; i++) pre[i * 500 + f] = (pre[i * 500 + f] - m) / sd * gf + bf;
    }
    __syncthreads();
    for (int idx = tid; idx < 2500; idx += 512) {
        int i = idx / 500, f = idx % 500;
        float mx = -1e30f;
#pragma unroll
        for (int j = 0; j < 5; j++)
            if (Mc[i * 5 + j] > 0.f || j == i) mx = fmaxf(mx, pre[j * 500 + f]);
        neigh[idx] = mx;
    }
    __syncthreads();
    for (int idx = tid; idx < 1250; idx += 512) {
        int i = idx / 250, o = idx % 250;
        const float* w = l1w + o * 500;
        float a0 = 0.f, a1 = 0.f, a2 = 0.f, a3 = 0.f;
        for (int k = 0; k < 500; k += 4) {
            a0 += neigh[i * 500 + k] * w[k];
            a1 += neigh[i * 500 + k + 1] * w[k + 1];
            a2 += neigh[i * 500 + k + 2] * w[k + 2];
            a3 += neigh[i * 500 + k + 3] * w[k + 3];
        }
        float acc = l1b[o] + ((a0 + a1) + (a2 + a3));
        h1[idx] = (acc >= 0.f) ? acc : 0.01f * acc;
    }
    __syncthreads();
    if (tid < 5) {
        float acc = l2b[0];
        for (int k = 0; k < 250; k++) acc += h1[tid * 250 + k] * l2w[k];
        lg[tid] = (acc >= 0.f) ? acc : 0.01f * acc;
    }
    __syncthreads();
    if (tid == 0) {
        float m = lg[0];
        for (int i = 1; i < 5; i++) m = fmaxf(m, lg[i]);
        float e[5], s = 0.f;
        for (int i = 0; i < 5; i++) { e[i] = expf(lg[i] - m); s += e[i]; }
        float p = 0.f;
        for (int i = 0; i < 5; i++) p = fmaxf(p, e[i] / s);
        out[0] = p;
        if (out_size > 1) out[1] = (p >= 0.5f) ? 1.f : 0.f;
    }
}

// ---------------- host launcher ----------------
static float* symaddr(const void* sym) {
    void* p = nullptr;
    cudaGetSymbolAddress(&p, sym);
    return (float*)p;
}

extern "C" void kernel_launch(void* const* d_in, const int* in_sizes, int n_in,
                              void* d_out, int out_size) {
    const float* x    = (const float*)d_in[0];
    const float* c1w  = (const float*)d_in[1];
    const float* c1b  = (const float*)d_in[2];
    const float* c2w  = (const float*)d_in[3];
    const float* c2b  = (const float*)d_in[4];
    const float* fcw  = (const float*)d_in[5];
    const float* fcb  = (const float*)d_in[6];
    const float* swl  = (const float*)d_in[7];
    const float* sbl  = (const float*)d_in[8];
    const float* swr  = (const float*)d_in[9];
    const float* bng  = (const float*)d_in[10];
    const float* bnb  = (const float*)d_in[11];
    const float* cgwo = (const float*)d_in[12];
    const float* cgbo = (const float*)d_in[13];
    const float* cgwr = (const float*)d_in[14];
    const float* l1w  = (const float*)d_in[15];
    const float* l1b  = (const float*)d_in[16];
    const float* l2w  = (const float*)d_in[17];
    const float* l2b  = (const float*)d_in[18];
    float* out = (float*)d_out;

    float* pF   = symaddr(g_F);
    float* pH   = symaddr(g_H);
    float* pAHn = symaddr(g_AHn);
    float* pZp  = symaddr(g_Zp);
    float* pW   = symaddr(g_W);

    const int c2_smem = C2_IMGS * 3840 * (int)sizeof(float);
    cudaFuncSetAttribute(k_conv2, cudaFuncAttributeMaxDynamicSharedMemorySize, c2_smem);

    k_zero<<<1, 64>>>();
    k_packw<<<512, 256>>>(swl, swr);
    k_packc1<<<1, 256>>>(c1w);
    k_packc2<<<25, 256>>>(c2w);
    k_conv1<<<NNODE, 384>>>(x, c1b);
    k_conv2<<<(NNODE + C2_IMGS - 1) / C2_IMGS, 512, c2_smem>>>(c2b);
    {   // fc: H = relu(F @ fcw^T + fcb), split-K 2 (400+400); fused row norms
        dim3 g(4, 32, 2);
        k_gemm_sk<<<g, 256>>>(pF, pF + 400, FEAT, fcw, fcw + 400, FEAT, 400, LL);
        k_comb<<<NNODE, 128>>>(fcb, pH, 1, 1);
    }
    k_gram<<<528, 256>>>();
    k_thr<<<1, 1>>>();
    k_adj<<<NNODE, 256>>>();
    k_gather<<<NNODE, 128>>>();
    {   // SAGE: Zp = leaky(AHn@wl^T + H@wr^T + bl), two slots of packed W
        dim3 g(4, 32, 2);
        k_gemm_sk<<<g, 256>>>(pAHn, pH, LP, pW, pW + 512, 1024, 512, LP);
        k_comb<<<NNODE, 128>>>(sbl, pZp, 2, 0);
    }
    k_bnsum<<<64, 512>>>();
    k_bnfin<<<1, 512>>>();
    k_cluster<<<NNODE / 4, 128>>>(cgwo, cgbo, cgwr);
    k_ts<<<NNODE / 8, 256>>>();
    {
        dim3 g(8, 8);
        k_coar<<<g, 256>>>(bng, bnb);
        k_coarfin<<<5, 512>>>();
    }
    k_ac<<<1, 256>>>();
    k_final<<<1, 512>>>(swl, sbl, swr, bng, bnb, l1w, l1b, l2w, l2b, out, out_size);
}